// round 1
// baseline (speedup 1.0000x reference)
#include <cuda_runtime.h>
#include <math.h>

// Problem constants
#define Bz 8
#define Tz 512
#define Ez 64
#define Hz 128
#define TC 32     // tokens per main-kernel CTA
#define NC 16     // chunks per batch (Tz/TC)
#define NCTA (Bz*NC)

// Per-CTA partial layout (floats)
#define OF_W1B 0
#define OF_W1D 8192
#define OF_B1B 16384
#define OF_B1D 16512
#define OF_W2B 16640
#define OF_W2D 24832
#define OF_B2B 33024
#define OF_B2D 33088
#define PARTSZ 33152

// Output offsets
#define O_LOSS 0
#define O_MW1  512
#define O_MB1  66048
#define O_MW2  67072
#define O_MB2  132608
#define O_SW1  133120
#define O_SB1  198656
#define O_SW2  199680
#define O_SB2  265216

// Scratch (device globals; no allocation allowed)
__device__ float g_sk[Bz*Tz*Ez];
__device__ float g_sv[Bz*Tz*Ez];
__device__ float g_nk[Bz*Ez];
__device__ float g_nv[Bz*Ez];
__device__ float g_cB[Tz];
__device__ float g_cD[Tz];
__device__ float g_scal[4];     // pT, A_T, qT
__device__ float g_lossp[Bz*Tz];
__device__ float g_part[NCTA*PARTSZ];

// ---------------------------------------------------------------------------
// K0: coefficients (double precision, matches fp32-cumprod reference within
// tolerance; beta^512 underflows to 0 in both) + zero the norm accumulators.
// ---------------------------------------------------------------------------
__global__ void k_init() {
    int tid = blockIdx.x * blockDim.x + threadIdx.x;
    if (tid < Bz*Ez) g_nk[tid] = 0.f;
    else if (tid < 2*Bz*Ez) g_nv[tid - Bz*Ez] = 0.f;
    if (tid == 0) {
        const double BETA = 1.0 - 0.999, ETA = 0.95, THETA = 0.05;
        double e = pow(ETA, 512.0);   // ETA^(t+1) at t=511
        double qT = e;
        double ps = 0.0;              // suffix sum of w
        double bp = 1.0;              // BETA^(511-t)
        double d  = ETA;              // ETA^(512-t)
        for (int t = Tz - 1; t >= 0; --t) {
            ps += bp * e;             // w[t] = BETA^(511-t)*ETA^(t+1)
            g_cB[t] = (float)(-THETA * ps / e);
            g_cD[t] = (float)(-THETA * d);
            bp *= BETA;
            d  *= ETA;
            e  /= ETA;
        }
        g_scal[0] = 0.0f;             // p_T = BETA^512 -> fp32 underflow -> 0
        g_scal[1] = (float)ps;        // A_T
        g_scal[2] = (float)qT;        // q_T
    }
}

// ---------------------------------------------------------------------------
// K1: s_k = silu(x @ WK^T), s_v = silu(x @ WV^T); accumulate sum of squares
// over T per (b,e). Grid: 128 CTAs (b*16+chunk), 256 threads.
// ---------------------------------------------------------------------------
__global__ __launch_bounds__(256) void k_proj(const float* __restrict__ x,
                                              const float* __restrict__ WK,
                                              const float* __restrict__ WV) {
    __shared__ float sWK[64*65], sWV[64*65], sx[TC*64], sk2[64], sv2[64];
    const int b  = blockIdx.x >> 4;
    const int t0 = (blockIdx.x & 15) * TC;
    const int tid = threadIdx.x;
    for (int i = tid; i < 4096; i += 256) {
        int e = i >> 6, j = i & 63;
        sWK[e*65 + j] = WK[i];
        sWV[e*65 + j] = WV[i];
    }
    for (int i = tid; i < TC*64; i += 256)
        sx[i] = x[(b*Tz + t0)*64 + i];
    if (tid < 64) { sk2[tid] = 0.f; sv2[tid] = 0.f; }
    __syncthreads();

    const int lane = tid & 31, wp = tid >> 5;   // 8 warps, 4 tokens each
    float acc[4][4];                            // [r over outputs][tt over tokens]
    #pragma unroll
    for (int r = 0; r < 4; r++)
        #pragma unroll
        for (int tt = 0; tt < 4; tt++) acc[r][tt] = 0.f;

    #pragma unroll 8
    for (int j = 0; j < 64; j++) {
        float wv[4], xv[4];
        wv[0] = sWK[(lane     )*65 + j];
        wv[1] = sWK[(lane + 32)*65 + j];
        wv[2] = sWV[(lane     )*65 + j];
        wv[3] = sWV[(lane + 32)*65 + j];
        #pragma unroll
        for (int tt = 0; tt < 4; tt++) xv[tt] = sx[(wp*4 + tt)*64 + j];
        #pragma unroll
        for (int r = 0; r < 4; r++)
            #pragma unroll
            for (int tt = 0; tt < 4; tt++) acc[r][tt] += wv[r] * xv[tt];
    }

    #pragma unroll
    for (int r = 0; r < 4; r++) {
        int e = lane + 32*(r & 1);
        float sq = 0.f;
        #pragma unroll
        for (int tt = 0; tt < 4; tt++) {
            float z = acc[r][tt];
            float s = z / (1.f + __expf(-z));       // silu
            int t = wp*4 + tt;
            if (r < 2) g_sk[(b*Tz + t0 + t)*64 + e] = s;
            else       g_sv[(b*Tz + t0 + t)*64 + e] = s;
            sq += s * s;
        }
        if (r < 2) atomicAdd(&sk2[e], sq);
        else       atomicAdd(&sv2[e], sq);
    }
    __syncthreads();
    if (tid < 64)       atomicAdd(&g_nk[b*64 + tid], sk2[tid]);
    else if (tid < 128) atomicAdd(&g_nv[b*64 + tid - 64], sv2[tid - 64]);
}

// ---------------------------------------------------------------------------
// K2: the heavy kernel. One CTA per (b, chunk of 32 tokens). 256 threads.
// Forward + backward per token, then weighted outer-product accumulation
// into per-CTA partials in registers.
// ---------------------------------------------------------------------------
#define SM_FLOATS 35232
__global__ __launch_bounds__(256, 1) void k_main(const float* __restrict__ W1,
                                                 const float* __restrict__ b1,
                                                 const float* __restrict__ W2,
                                                 const float* __restrict__ b2) {
    extern __shared__ float sm[];
    float* sW1  = sm;                 // 128 x pitch65  = 8320
    float* sW2  = sW1 + 8320;         // 64  x pitch129 = 8256
    float* sk   = sW2 + 8256;         // 32x64
    float* sv   = sk  + 2048;         // 32x64
    float* sh   = sv  + 2048;         // 32x128
    float* ss   = sh  + 4096;         // 32x128
    float* sdy  = ss  + 4096;         // 32x64
    float* sdz  = sdy + 2048;         // 32x128
    float* scB  = sdz + 4096;         // 32
    float* scD  = scB + 32;           // 32
    float* sinvk= scD + 32;           // 64
    float* sinvv= sinvk + 64;         // 64
    float* sloss= sinvv + 64;         // 32

    const int b  = blockIdx.x >> 4;
    const int t0 = (blockIdx.x & 15) * TC;
    const int tid = threadIdx.x;
    const int lane = tid & 31, wp = tid >> 5;

    for (int i = tid; i < 8192; i += 256)
        sW1[(i >> 6)*65 + (i & 63)] = W1[b*8192 + i];
    for (int i = tid; i < 8192; i += 256)
        sW2[(i >> 7)*129 + (i & 127)] = W2[b*8192 + i];
    if (tid < 64) {
        float s  = g_nk[b*64 + tid];
        sinvk[tid] = (s > 0.f) ? rsqrtf(s) : 0.f;   // 1/max(||.||,1e-12)
        float s2 = g_nv[b*64 + tid];
        sinvv[tid] = (s2 > 0.f) ? rsqrtf(s2) : 0.f;
    }
    if (tid >= 64 && tid < 96) {
        scB[tid - 64] = g_cB[t0 + tid - 64];
        scD[tid - 64] = g_cD[t0 + tid - 64];
    }
    __syncthreads();

    for (int i = tid; i < 2048; i += 256) {
        int t = i >> 6, e = i & 63;
        sk[i] = g_sk[(b*Tz + t0 + t)*64 + e] * sinvk[e];
        sv[i] = g_sv[(b*Tz + t0 + t)*64 + e] * sinvv[e];
    }
    __syncthreads();

    // ---- z = W1 k + b1 ; h = silu(z); stash sigmoid too ----
    {
        float bv[4];
        #pragma unroll
        for (int r = 0; r < 4; r++) bv[r] = b1[b*128 + lane + 32*r];
        float acc[4][4];
        #pragma unroll
        for (int r = 0; r < 4; r++)
            #pragma unroll
            for (int tt = 0; tt < 4; tt++) acc[r][tt] = bv[r];
        #pragma unroll 8
        for (int j = 0; j < 64; j++) {
            float wv[4], kv[4];
            #pragma unroll
            for (int r = 0; r < 4; r++) wv[r] = sW1[(lane + 32*r)*65 + j];
            #pragma unroll
            for (int tt = 0; tt < 4; tt++) kv[tt] = sk[(wp*4 + tt)*64 + j];
            #pragma unroll
            for (int r = 0; r < 4; r++)
                #pragma unroll
                for (int tt = 0; tt < 4; tt++) acc[r][tt] += wv[r] * kv[tt];
        }
        #pragma unroll
        for (int r = 0; r < 4; r++)
            #pragma unroll
            for (int tt = 0; tt < 4; tt++) {
                int idx = (wp*4 + tt)*128 + lane + 32*r;
                float z  = acc[r][tt];
                float sg = 1.f / (1.f + __expf(-z));
                ss[idx] = sg;
                sh[idx] = z * sg;
            }
    }
    __syncthreads();

    // ---- y = W2 h + b2 ; dy = (y - v)/256 ; per-token loss ----
    {
        float bv[2];
        bv[0] = b2[b*64 + lane];
        bv[1] = b2[b*64 + lane + 32];
        float acc[2][4];
        #pragma unroll
        for (int r = 0; r < 2; r++)
            #pragma unroll
            for (int tt = 0; tt < 4; tt++) acc[r][tt] = bv[r];
        #pragma unroll 8
        for (int j = 0; j < 128; j++) {
            float wv[2], hv[4];
            wv[0] = sW2[(lane     )*129 + j];
            wv[1] = sW2[(lane + 32)*129 + j];
            #pragma unroll
            for (int tt = 0; tt < 4; tt++) hv[tt] = sh[(wp*4 + tt)*128 + j];
            #pragma unroll
            for (int r = 0; r < 2; r++)
                #pragma unroll
                for (int tt = 0; tt < 4; tt++) acc[r][tt] += wv[r] * hv[tt];
        }
        #pragma unroll
        for (int tt = 0; tt < 4; tt++) {
            int t = wp*4 + tt;
            float l = 0.f;
            #pragma unroll
            for (int r = 0; r < 2; r++) {
                int e = lane + 32*r;
                float d = acc[r][tt] - sv[t*64 + e];
                sdy[t*64 + e] = d * (1.f/256.f);
                l += d * d;
            }
            #pragma unroll
            for (int o = 16; o; o >>= 1) l += __shfl_xor_sync(0xffffffffu, l, o);
            if (lane == 0) sloss[t] = l;   // each t owned by one warp
        }
    }
    __syncthreads();

    // ---- dh = W2^T dy ; dz = dh * dsilu ----
    {
        float acc[4][4];
        #pragma unroll
        for (int r = 0; r < 4; r++)
            #pragma unroll
            for (int tt = 0; tt < 4; tt++) acc[r][tt] = 0.f;
        #pragma unroll 8
        for (int e = 0; e < 64; e++) {
            float wv[4], dv[4];
            #pragma unroll
            for (int r = 0; r < 4; r++) wv[r] = sW2[e*129 + lane + 32*r];
            #pragma unroll
            for (int tt = 0; tt < 4; tt++) dv[tt] = sdy[(wp*4 + tt)*64 + e];
            #pragma unroll
            for (int r = 0; r < 4; r++)
                #pragma unroll
                for (int tt = 0; tt < 4; tt++) acc[r][tt] += wv[r] * dv[tt];
        }
        #pragma unroll
        for (int r = 0; r < 4; r++)
            #pragma unroll
            for (int tt = 0; tt < 4; tt++) {
                int idx = (wp*4 + tt)*128 + lane + 32*r;
                float sg = ss[idx], hv = sh[idx];
                // dsilu(z) = sg + z*sg*(1-sg) = sg + h*(1-sg)
                sdz[idx] = acc[r][tt] * (sg + hv * (1.f - sg));
            }
    }
    __syncthreads();

    // ---- weighted outer-product accumulation (rank-32 per CTA) ----
    const int tx = tid & 15;   // e tile base
    const int ty = tid >> 4;   // h tile base
    float aW1B[8][4], aW1D[8][4], aW2B[4][8], aW2D[4][8];
    #pragma unroll
    for (int i = 0; i < 8; i++)
        #pragma unroll
        for (int j = 0; j < 4; j++) { aW1B[i][j] = 0.f; aW1D[i][j] = 0.f; }
    #pragma unroll
    for (int j = 0; j < 4; j++)
        #pragma unroll
        for (int i = 0; i < 8; i++) { aW2B[j][i] = 0.f; aW2D[j][i] = 0.f; }

    for (int t = 0; t < TC; t++) {
        float cB = scB[t], cD = scD[t];
        float dzv[8], kv[4];
        #pragma unroll
        for (int i = 0; i < 8; i++) dzv[i] = sdz[t*128 + ty + 16*i];
        #pragma unroll
        for (int j = 0; j < 4; j++) kv[j] = sk[t*64 + tx + 16*j];
        #pragma unroll
        for (int i = 0; i < 8; i++) {
            float pB = cB * dzv[i], pD = cD * dzv[i];
            #pragma unroll
            for (int j = 0; j < 4; j++) {
                aW1B[i][j] += pB * kv[j];
                aW1D[i][j] += pD * kv[j];
            }
        }
        float dyv[4], hv[8];
        #pragma unroll
        for (int j = 0; j < 4; j++) dyv[j] = sdy[t*64 + tx + 16*j];
        #pragma unroll
        for (int i = 0; i < 8; i++) hv[i] = sh[t*128 + ty + 16*i];
        #pragma unroll
        for (int j = 0; j < 4; j++) {
            float pB = cB * dyv[j], pD = cD * dyv[j];
            #pragma unroll
            for (int i = 0; i < 8; i++) {
                aW2B[j][i] += pB * hv[i];
                aW2D[j][i] += pD * hv[i];
            }
        }
    }

    float* p = g_part + (size_t)blockIdx.x * PARTSZ;
    #pragma unroll
    for (int i = 0; i < 8; i++)
        #pragma unroll
        for (int j = 0; j < 4; j++) {
            int h = ty + 16*i, e = tx + 16*j;
            p[OF_W1B + h*64 + e] = aW1B[i][j];
            p[OF_W1D + h*64 + e] = aW1D[i][j];
        }
    #pragma unroll
    for (int j = 0; j < 4; j++)
        #pragma unroll
        for (int i = 0; i < 8; i++) {
            int e = tx + 16*j, h = ty + 16*i;
            p[OF_W2B + e*128 + h] = aW2B[j][i];
            p[OF_W2D + e*128 + h] = aW2D[j][i];
        }
    if (tid < 128) {
        float aB = 0.f, aD = 0.f;
        for (int t = 0; t < TC; t++) {
            float d = sdz[t*128 + tid];
            aB += scB[t] * d; aD += scD[t] * d;
        }
        p[OF_B1B + tid] = aB;
        p[OF_B1D + tid] = aD;
    } else if (tid < 192) {
        int e = tid - 128;
        float aB = 0.f, aD = 0.f;
        for (int t = 0; t < TC; t++) {
            float d = sdy[t*64 + e];
            aB += scB[t] * d; aD += scD[t] * d;
        }
        p[OF_B2B + e] = aB;
        p[OF_B2D + e] = aD;
    }
    if (tid < TC) g_lossp[b*Tz + t0 + tid] = sloss[tid];
}

// ---------------------------------------------------------------------------
// K3: reduce partials, apply state transforms, write the output vector.
// ---------------------------------------------------------------------------
__global__ __launch_bounds__(256) void k_final(const float* __restrict__ W1,
                                               const float* __restrict__ b1,
                                               const float* __restrict__ W2,
                                               const float* __restrict__ b2,
                                               const float* __restrict__ SW1,
                                               const float* __restrict__ Sb1,
                                               const float* __restrict__ SW2,
                                               const float* __restrict__ Sb2,
                                               float* __restrict__ out) {
    int i = blockIdx.x * blockDim.x + threadIdx.x;
    const float pT = g_scal[0], aT = g_scal[1], qT = g_scal[2];
    if (i < 512) {
        float s = 0.f;
        #pragma unroll
        for (int b = 0; b < Bz; b++) s += g_lossp[b*Tz + i];
        out[O_LOSS + i] = s * (1.f/512.f);
        return;
    }
    int j = i - 512;
    if (j < 65536) {  // W1
        int b = j >> 13, r = j & 8191;
        const float* p = g_part + (size_t)(b*NC) * PARTSZ;
        float rB = 0.f, rD = 0.f;
        #pragma unroll
        for (int c = 0; c < NC; c++) {
            rB += p[(size_t)c*PARTSZ + OF_W1B + r];
            rD += p[(size_t)c*PARTSZ + OF_W1D + r];
        }
        out[O_MW1 + j] = pT*W1[j] + aT*SW1[j] + rB;
        out[O_SW1 + j] = qT*SW1[j] + rD;
        return;
    }
    j -= 65536;
    if (j < 1024) {   // b1
        int b = j >> 7, r = j & 127;
        const float* p = g_part + (size_t)(b*NC) * PARTSZ;
        float rB = 0.f, rD = 0.f;
        #pragma unroll
        for (int c = 0; c < NC; c++) {
            rB += p[(size_t)c*PARTSZ + OF_B1B + r];
            rD += p[(size_t)c*PARTSZ + OF_B1D + r];
        }
        out[O_MB1 + j] = pT*b1[j] + aT*Sb1[j] + rB;
        out[O_SB1 + j] = qT*Sb1[j] + rD;
        return;
    }
    j -= 1024;
    if (j < 65536) {  // W2
        int b = j >> 13, r = j & 8191;
        const float* p = g_part + (size_t)(b*NC) * PARTSZ;
        float rB = 0.f, rD = 0.f;
        #pragma unroll
        for (int c = 0; c < NC; c++) {
            rB += p[(size_t)c*PARTSZ + OF_W2B + r];
            rD += p[(size_t)c*PARTSZ + OF_W2D + r];
        }
        out[O_MW2 + j] = pT*W2[j] + aT*SW2[j] + rB;
        out[O_SW2 + j] = qT*SW2[j] + rD;
        return;
    }
    j -= 65536;
    if (j < 512) {    // b2
        int b = j >> 6, r = j & 63;
        const float* p = g_part + (size_t)(b*NC) * PARTSZ;
        float rB = 0.f, rD = 0.f;
        #pragma unroll
        for (int c = 0; c < NC; c++) {
            rB += p[(size_t)c*PARTSZ + OF_B2B + r];
            rD += p[(size_t)c*PARTSZ + OF_B2D + r];
        }
        out[O_MB2 + j] = pT*b2[j] + aT*Sb2[j] + rB;
        out[O_SB2 + j] = qT*Sb2[j] + rD;
    }
}

extern "C" void kernel_launch(void* const* d_in, const int* in_sizes, int n_in,
                              void* d_out, int out_size) {
    const float* x   = (const float*)d_in[0];
    const float* WK  = (const float*)d_in[1];
    const float* WV  = (const float*)d_in[2];
    const float* W1  = (const float*)d_in[3];
    const float* b1  = (const float*)d_in[4];
    const float* W2  = (const float*)d_in[5];
    const float* b2  = (const float*)d_in[6];
    const float* SW1 = (const float*)d_in[7];
    const float* Sb1 = (const float*)d_in[8];
    const float* SW2 = (const float*)d_in[9];
    const float* Sb2 = (const float*)d_in[10];
    float* out = (float*)d_out;

    static const size_t smem_main = SM_FLOATS * sizeof(float);
    cudaFuncSetAttribute(k_main, cudaFuncAttributeMaxDynamicSharedMemorySize,
                         (int)smem_main);

    k_init<<<4, 256>>>();
    k_proj<<<NCTA, 256>>>(x, WK, WV);
    k_main<<<NCTA, 256, smem_main>>>(W1, b1, W2, b2);
    k_final<<<(512 + 132608 + 255) / 256, 256>>>(W1, b1, W2, b2,
                                                 SW1, Sb1, SW2, Sb2, out);
}

// round 2
// speedup vs baseline: 7.0811x; 7.0811x over previous
#include <cuda_runtime.h>
#include <math.h>

// Problem constants
#define Bz 8
#define Tz 512
#define Ez 64
#define Hz 128
#define TC 32     // tokens per main-kernel CTA
#define NC 16     // chunks per batch (Tz/TC)
#define NCTA (Bz*NC)

// Per-CTA partial layout (floats)
#define OF_W1B 0
#define OF_W1D 8192
#define OF_B1B 16384
#define OF_B1D 16512
#define OF_W2B 16640
#define OF_W2D 24832
#define OF_B2B 33024
#define OF_B2D 33088
#define PARTSZ 33152

// Output offsets
#define O_LOSS 0
#define O_MW1  512
#define O_MB1  66048
#define O_MW2  67072
#define O_MB2  132608
#define O_SW1  133120
#define O_SB1  198656
#define O_SW2  199680
#define O_SB2  265216

// Scratch (device globals; no allocation allowed)
__device__ float g_sk[Bz*Tz*Ez];
__device__ float g_sv[Bz*Tz*Ez];
__device__ float g_nk[Bz*Ez];
__device__ float g_nv[Bz*Ez];
__device__ float g_cB[Tz];
__device__ float g_cD[Tz];
__device__ float g_scal[4];     // pT, A_T, qT
__device__ float g_lossp[Bz*Tz];
__device__ float g_part[NCTA*PARTSZ];

// ---------------------------------------------------------------------------
// K0: coefficients via CLOSED FORM, fully parallel (one thread per t).
//   n = 511 - t
//   cB[t] = -theta * (eta^{n+1} - beta^{n+1}) / (eta - beta)
//   cD[t] = -theta * eta^{n+1}
//   A_T   = eta^512 * (1 - (beta/eta)^512) / (1 - beta/eta)
//   q_T   = eta^512 ;  p_T = beta^512 -> 0 (fp32/fp64 underflow)
// Also zeros the norm accumulators.
// ---------------------------------------------------------------------------
__global__ void k_init() {
    int tid = blockIdx.x * blockDim.x + threadIdx.x;
    if (tid < Bz*Ez) g_nk[tid] = 0.f;
    else if (tid < 2*Bz*Ez) g_nv[tid - Bz*Ez] = 0.f;

    const double BETA = 1.0 - 0.999, ETA = 0.95, THETA = 0.05;
    if (tid < Tz) {
        int n1 = Tz - tid;                 // n+1
        double ep = pow(ETA, (double)n1);
        double bp = pow(BETA, (double)n1); // underflows to 0 for n1 > ~100
        g_cB[tid] = (float)(-THETA * (ep - bp) / (ETA - BETA));
        g_cD[tid] = (float)(-THETA * ep);
    }
    if (tid == 0) {
        double qT = pow(ETA, 512.0);
        double r  = BETA / ETA;
        double aT = qT * (1.0 - pow(r, 512.0)) / (1.0 - r);
        g_scal[0] = 0.0f;          // p_T
        g_scal[1] = (float)aT;     // A_T
        g_scal[2] = (float)qT;     // q_T
    }
}

// ---------------------------------------------------------------------------
// K1: s_k = silu(x @ WK^T), s_v = silu(x @ WV^T); accumulate sum of squares
// over T per (b,e). Grid: 128 CTAs (b*16+chunk), 256 threads.
// ---------------------------------------------------------------------------
__global__ __launch_bounds__(256) void k_proj(const float* __restrict__ x,
                                              const float* __restrict__ WK,
                                              const float* __restrict__ WV) {
    __shared__ float sWK[64*65], sWV[64*65], sx[TC*64], sk2[64], sv2[64];
    const int b  = blockIdx.x >> 4;
    const int t0 = (blockIdx.x & 15) * TC;
    const int tid = threadIdx.x;
    for (int i = tid; i < 4096; i += 256) {
        int e = i >> 6, j = i & 63;
        sWK[e*65 + j] = WK[i];
        sWV[e*65 + j] = WV[i];
    }
    for (int i = tid; i < TC*64; i += 256)
        sx[i] = x[(b*Tz + t0)*64 + i];
    if (tid < 64) { sk2[tid] = 0.f; sv2[tid] = 0.f; }
    __syncthreads();

    const int lane = tid & 31, wp = tid >> 5;   // 8 warps, 4 tokens each
    float acc[4][4];                            // [r over outputs][tt over tokens]
    #pragma unroll
    for (int r = 0; r < 4; r++)
        #pragma unroll
        for (int tt = 0; tt < 4; tt++) acc[r][tt] = 0.f;

    #pragma unroll 8
    for (int j = 0; j < 64; j++) {
        float wv[4], xv[4];
        wv[0] = sWK[(lane     )*65 + j];
        wv[1] = sWK[(lane + 32)*65 + j];
        wv[2] = sWV[(lane     )*65 + j];
        wv[3] = sWV[(lane + 32)*65 + j];
        #pragma unroll
        for (int tt = 0; tt < 4; tt++) xv[tt] = sx[(wp*4 + tt)*64 + j];
        #pragma unroll
        for (int r = 0; r < 4; r++)
            #pragma unroll
            for (int tt = 0; tt < 4; tt++) acc[r][tt] += wv[r] * xv[tt];
    }

    #pragma unroll
    for (int r = 0; r < 4; r++) {
        int e = lane + 32*(r & 1);
        float sq = 0.f;
        #pragma unroll
        for (int tt = 0; tt < 4; tt++) {
            float z = acc[r][tt];
            float s = z / (1.f + __expf(-z));       // silu
            int t = wp*4 + tt;
            if (r < 2) g_sk[(b*Tz + t0 + t)*64 + e] = s;
            else       g_sv[(b*Tz + t0 + t)*64 + e] = s;
            sq += s * s;
        }
        if (r < 2) atomicAdd(&sk2[e], sq);
        else       atomicAdd(&sv2[e], sq);
    }
    __syncthreads();
    if (tid < 64)       atomicAdd(&g_nk[b*64 + tid], sk2[tid]);
    else if (tid < 128) atomicAdd(&g_nv[b*64 + tid - 64], sv2[tid - 64]);
}

// ---------------------------------------------------------------------------
// K2: the heavy kernel. One CTA per (b, chunk of 32 tokens). 256 threads.
// Forward + backward per token, then weighted outer-product accumulation
// into per-CTA partials in registers.
// ---------------------------------------------------------------------------
#define SM_FLOATS 35232
__global__ __launch_bounds__(256, 1) void k_main(const float* __restrict__ W1,
                                                 const float* __restrict__ b1,
                                                 const float* __restrict__ W2,
                                                 const float* __restrict__ b2) {
    extern __shared__ float sm[];
    float* sW1  = sm;                 // 128 x pitch65  = 8320
    float* sW2  = sW1 + 8320;         // 64  x pitch129 = 8256
    float* sk   = sW2 + 8256;         // 32x64
    float* sv   = sk  + 2048;         // 32x64
    float* sh   = sv  + 2048;         // 32x128
    float* ss   = sh  + 4096;         // 32x128
    float* sdy  = ss  + 4096;         // 32x64
    float* sdz  = sdy + 2048;         // 32x128
    float* scB  = sdz + 4096;         // 32
    float* scD  = scB + 32;           // 32
    float* sinvk= scD + 32;           // 64
    float* sinvv= sinvk + 64;         // 64
    float* sloss= sinvv + 64;         // 32

    const int b  = blockIdx.x >> 4;
    const int t0 = (blockIdx.x & 15) * TC;
    const int tid = threadIdx.x;
    const int lane = tid & 31, wp = tid >> 5;

    for (int i = tid; i < 8192; i += 256)
        sW1[(i >> 6)*65 + (i & 63)] = W1[b*8192 + i];
    for (int i = tid; i < 8192; i += 256)
        sW2[(i >> 7)*129 + (i & 127)] = W2[b*8192 + i];
    if (tid < 64) {
        float s  = g_nk[b*64 + tid];
        sinvk[tid] = (s > 0.f) ? rsqrtf(s) : 0.f;   // 1/max(||.||,1e-12)
        float s2 = g_nv[b*64 + tid];
        sinvv[tid] = (s2 > 0.f) ? rsqrtf(s2) : 0.f;
    }
    if (tid >= 64 && tid < 96) {
        scB[tid - 64] = g_cB[t0 + tid - 64];
        scD[tid - 64] = g_cD[t0 + tid - 64];
    }
    __syncthreads();

    for (int i = tid; i < 2048; i += 256) {
        int t = i >> 6, e = i & 63;
        sk[i] = g_sk[(b*Tz + t0 + t)*64 + e] * sinvk[e];
        sv[i] = g_sv[(b*Tz + t0 + t)*64 + e] * sinvv[e];
    }
    __syncthreads();

    // ---- z = W1 k + b1 ; h = silu(z); stash sigmoid too ----
    {
        float bv[4];
        #pragma unroll
        for (int r = 0; r < 4; r++) bv[r] = b1[b*128 + lane + 32*r];
        float acc[4][4];
        #pragma unroll
        for (int r = 0; r < 4; r++)
            #pragma unroll
            for (int tt = 0; tt < 4; tt++) acc[r][tt] = bv[r];
        #pragma unroll 8
        for (int j = 0; j < 64; j++) {
            float wv[4], kv[4];
            #pragma unroll
            for (int r = 0; r < 4; r++) wv[r] = sW1[(lane + 32*r)*65 + j];
            #pragma unroll
            for (int tt = 0; tt < 4; tt++) kv[tt] = sk[(wp*4 + tt)*64 + j];
            #pragma unroll
            for (int r = 0; r < 4; r++)
                #pragma unroll
                for (int tt = 0; tt < 4; tt++) acc[r][tt] += wv[r] * kv[tt];
        }
        #pragma unroll
        for (int r = 0; r < 4; r++)
            #pragma unroll
            for (int tt = 0; tt < 4; tt++) {
                int idx = (wp*4 + tt)*128 + lane + 32*r;
                float z  = acc[r][tt];
                float sg = 1.f / (1.f + __expf(-z));
                ss[idx] = sg;
                sh[idx] = z * sg;
            }
    }
    __syncthreads();

    // ---- y = W2 h + b2 ; dy = (y - v)/256 ; per-token loss ----
    {
        float bv[2];
        bv[0] = b2[b*64 + lane];
        bv[1] = b2[b*64 + lane + 32];
        float acc[2][4];
        #pragma unroll
        for (int r = 0; r < 2; r++)
            #pragma unroll
            for (int tt = 0; tt < 4; tt++) acc[r][tt] = bv[r];
        #pragma unroll 8
        for (int j = 0; j < 128; j++) {
            float wv[2], hv[4];
            wv[0] = sW2[(lane     )*129 + j];
            wv[1] = sW2[(lane + 32)*129 + j];
            #pragma unroll
            for (int tt = 0; tt < 4; tt++) hv[tt] = sh[(wp*4 + tt)*128 + j];
            #pragma unroll
            for (int r = 0; r < 2; r++)
                #pragma unroll
                for (int tt = 0; tt < 4; tt++) acc[r][tt] += wv[r] * hv[tt];
        }
        #pragma unroll
        for (int tt = 0; tt < 4; tt++) {
            int t = wp*4 + tt;
            float l = 0.f;
            #pragma unroll
            for (int r = 0; r < 2; r++) {
                int e = lane + 32*r;
                float d = acc[r][tt] - sv[t*64 + e];
                sdy[t*64 + e] = d * (1.f/256.f);
                l += d * d;
            }
            #pragma unroll
            for (int o = 16; o; o >>= 1) l += __shfl_xor_sync(0xffffffffu, l, o);
            if (lane == 0) sloss[t] = l;   // each t owned by one warp
        }
    }
    __syncthreads();

    // ---- dh = W2^T dy ; dz = dh * dsilu ----
    {
        float acc[4][4];
        #pragma unroll
        for (int r = 0; r < 4; r++)
            #pragma unroll
            for (int tt = 0; tt < 4; tt++) acc[r][tt] = 0.f;
        #pragma unroll 8
        for (int e = 0; e < 64; e++) {
            float wv[4], dv[4];
            #pragma unroll
            for (int r = 0; r < 4; r++) wv[r] = sW2[e*129 + lane + 32*r];
            #pragma unroll
            for (int tt = 0; tt < 4; tt++) dv[tt] = sdy[(wp*4 + tt)*64 + e];
            #pragma unroll
            for (int r = 0; r < 4; r++)
                #pragma unroll
                for (int tt = 0; tt < 4; tt++) acc[r][tt] += wv[r] * dv[tt];
        }
        #pragma unroll
        for (int r = 0; r < 4; r++)
            #pragma unroll
            for (int tt = 0; tt < 4; tt++) {
                int idx = (wp*4 + tt)*128 + lane + 32*r;
                float sg = ss[idx], hv = sh[idx];
                // dsilu(z) = sg + z*sg*(1-sg) = sg + h*(1-sg)
                sdz[idx] = acc[r][tt] * (sg + hv * (1.f - sg));
            }
    }
    __syncthreads();

    // ---- weighted outer-product accumulation (rank-32 per CTA) ----
    const int tx = tid & 15;   // e tile base
    const int ty = tid >> 4;   // h tile base
    float aW1B[8][4], aW1D[8][4], aW2B[4][8], aW2D[4][8];
    #pragma unroll
    for (int i = 0; i < 8; i++)
        #pragma unroll
        for (int j = 0; j < 4; j++) { aW1B[i][j] = 0.f; aW1D[i][j] = 0.f; }
    #pragma unroll
    for (int j = 0; j < 4; j++)
        #pragma unroll
        for (int i = 0; i < 8; i++) { aW2B[j][i] = 0.f; aW2D[j][i] = 0.f; }

    for (int t = 0; t < TC; t++) {
        float cB = scB[t], cD = scD[t];
        float dzv[8], kv[4];
        #pragma unroll
        for (int i = 0; i < 8; i++) dzv[i] = sdz[t*128 + ty + 16*i];
        #pragma unroll
        for (int j = 0; j < 4; j++) kv[j] = sk[t*64 + tx + 16*j];
        #pragma unroll
        for (int i = 0; i < 8; i++) {
            float pB = cB * dzv[i], pD = cD * dzv[i];
            #pragma unroll
            for (int j = 0; j < 4; j++) {
                aW1B[i][j] += pB * kv[j];
                aW1D[i][j] += pD * kv[j];
            }
        }
        float dyv[4], hv[8];
        #pragma unroll
        for (int j = 0; j < 4; j++) dyv[j] = sdy[t*64 + tx + 16*j];
        #pragma unroll
        for (int i = 0; i < 8; i++) hv[i] = sh[t*128 + ty + 16*i];
        #pragma unroll
        for (int j = 0; j < 4; j++) {
            float pB = cB * dyv[j], pD = cD * dyv[j];
            #pragma unroll
            for (int i = 0; i < 8; i++) {
                aW2B[j][i] += pB * hv[i];
                aW2D[j][i] += pD * hv[i];
            }
        }
    }

    float* p = g_part + (size_t)blockIdx.x * PARTSZ;
    #pragma unroll
    for (int i = 0; i < 8; i++)
        #pragma unroll
        for (int j = 0; j < 4; j++) {
            int h = ty + 16*i, e = tx + 16*j;
            p[OF_W1B + h*64 + e] = aW1B[i][j];
            p[OF_W1D + h*64 + e] = aW1D[i][j];
        }
    #pragma unroll
    for (int j = 0; j < 4; j++)
        #pragma unroll
        for (int i = 0; i < 8; i++) {
            int e = tx + 16*j, h = ty + 16*i;
            p[OF_W2B + e*128 + h] = aW2B[j][i];
            p[OF_W2D + e*128 + h] = aW2D[j][i];
        }
    if (tid < 128) {
        float aB = 0.f, aD = 0.f;
        for (int t = 0; t < TC; t++) {
            float d = sdz[t*128 + tid];
            aB += scB[t] * d; aD += scD[t] * d;
        }
        p[OF_B1B + tid] = aB;
        p[OF_B1D + tid] = aD;
    } else if (tid < 192) {
        int e = tid - 128;
        float aB = 0.f, aD = 0.f;
        for (int t = 0; t < TC; t++) {
            float d = sdy[t*64 + e];
            aB += scB[t] * d; aD += scD[t] * d;
        }
        p[OF_B2B + e] = aB;
        p[OF_B2D + e] = aD;
    }
    if (tid < TC) g_lossp[b*Tz + t0 + tid] = sloss[tid];
}

// ---------------------------------------------------------------------------
// K3: reduce partials, apply state transforms, write the output vector.
// ---------------------------------------------------------------------------
__global__ __launch_bounds__(256) void k_final(const float* __restrict__ W1,
                                               const float* __restrict__ b1,
                                               const float* __restrict__ W2,
                                               const float* __restrict__ b2,
                                               const float* __restrict__ SW1,
                                               const float* __restrict__ Sb1,
                                               const float* __restrict__ SW2,
                                               const float* __restrict__ Sb2,
                                               float* __restrict__ out) {
    int i = blockIdx.x * blockDim.x + threadIdx.x;
    const float pT = g_scal[0], aT = g_scal[1], qT = g_scal[2];
    if (i < 512) {
        float s = 0.f;
        #pragma unroll
        for (int b = 0; b < Bz; b++) s += g_lossp[b*Tz + i];
        out[O_LOSS + i] = s * (1.f/512.f);
        return;
    }
    int j = i - 512;
    if (j < 65536) {  // W1
        int b = j >> 13, r = j & 8191;
        const float* p = g_part + (size_t)(b*NC) * PARTSZ;
        float rB = 0.f, rD = 0.f;
        #pragma unroll
        for (int c = 0; c < NC; c++) {
            rB += p[(size_t)c*PARTSZ + OF_W1B + r];
            rD += p[(size_t)c*PARTSZ + OF_W1D + r];
        }
        out[O_MW1 + j] = pT*W1[j] + aT*SW1[j] + rB;
        out[O_SW1 + j] = qT*SW1[j] + rD;
        return;
    }
    j -= 65536;
    if (j < 1024) {   // b1
        int b = j >> 7, r = j & 127;
        const float* p = g_part + (size_t)(b*NC) * PARTSZ;
        float rB = 0.f, rD = 0.f;
        #pragma unroll
        for (int c = 0; c < NC; c++) {
            rB += p[(size_t)c*PARTSZ + OF_B1B + r];
            rD += p[(size_t)c*PARTSZ + OF_B1D + r];
        }
        out[O_MB1 + j] = pT*b1[j] + aT*Sb1[j] + rB;
        out[O_SB1 + j] = qT*Sb1[j] + rD;
        return;
    }
    j -= 1024;
    if (j < 65536) {  // W2
        int b = j >> 13, r = j & 8191;
        const float* p = g_part + (size_t)(b*NC) * PARTSZ;
        float rB = 0.f, rD = 0.f;
        #pragma unroll
        for (int c = 0; c < NC; c++) {
            rB += p[(size_t)c*PARTSZ + OF_W2B + r];
            rD += p[(size_t)c*PARTSZ + OF_W2D + r];
        }
        out[O_MW2 + j] = pT*W2[j] + aT*SW2[j] + rB;
        out[O_SW2 + j] = qT*SW2[j] + rD;
        return;
    }
    j -= 65536;
    if (j < 512) {    // b2
        int b = j >> 6, r = j & 63;
        const float* p = g_part + (size_t)(b*NC) * PARTSZ;
        float rB = 0.f, rD = 0.f;
        #pragma unroll
        for (int c = 0; c < NC; c++) {
            rB += p[(size_t)c*PARTSZ + OF_B2B + r];
            rD += p[(size_t)c*PARTSZ + OF_B2D + r];
        }
        out[O_MB2 + j] = pT*b2[j] + aT*Sb2[j] + rB;
        out[O_SB2 + j] = qT*Sb2[j] + rD;
    }
}

extern "C" void kernel_launch(void* const* d_in, const int* in_sizes, int n_in,
                              void* d_out, int out_size) {
    const float* x   = (const float*)d_in[0];
    const float* WK  = (const float*)d_in[1];
    const float* WV  = (const float*)d_in[2];
    const float* W1  = (const float*)d_in[3];
    const float* b1  = (const float*)d_in[4];
    const float* W2  = (const float*)d_in[5];
    const float* b2  = (const float*)d_in[6];
    const float* SW1 = (const float*)d_in[7];
    const float* Sb1 = (const float*)d_in[8];
    const float* SW2 = (const float*)d_in[9];
    const float* Sb2 = (const float*)d_in[10];
    float* out = (float*)d_out;

    static const size_t smem_main = SM_FLOATS * sizeof(float);
    cudaFuncSetAttribute(k_main, cudaFuncAttributeMaxDynamicSharedMemorySize,
                         (int)smem_main);

    k_init<<<4, 256>>>();
    k_proj<<<NCTA, 256>>>(x, WK, WV);
    k_main<<<NCTA, 256, smem_main>>>(W1, b1, W2, b2);
    k_final<<<(512 + 132608 + 255) / 256, 256>>>(W1, b1, W2, b2,
                                                 SW1, Sb1, SW2, Sb2, out);
}

// round 3
// speedup vs baseline: 11.3210x; 1.5988x over previous
#include <cuda_runtime.h>
#include <math.h>

// Problem constants
#define Bz 8
#define Tz 512
#define Ez 64
#define Hz 128
#define TC 32     // tokens per main-kernel CTA
#define NC 16     // chunks per batch (Tz/TC)
#define NCTA (Bz*NC)

// Per-CTA partial layout (floats): D-weighted grads only
#define OF2_W1D 0
#define OF2_B1D 8192
#define OF2_W2D 8320
#define OF2_B2D 16512
#define PARTSZ2 16576

// Output offsets
#define O_LOSS 0
#define O_MW1  512
#define O_MB1  66048
#define O_MW2  67072
#define O_MB2  132608
#define O_SW1  133120
#define O_SB1  198656
#define O_SW2  199680
#define O_SB2  265216

// Constants:  cB[t] = cD[t]*INV949 + corrC[t],  corrC = (theta/(eta-beta))*beta^n1
#define LNETA  (-0.0512932943875506f)   // ln(0.95)
#define LNBETA (-6.9077552789821370f)   // ln(0.001)
#define INV949 (1.0537407798735f)       // 1/(0.95-0.001)
#define CORRK  (0.0526870389936f)       // 0.05/(0.949)

// Scratch (device globals; no allocation allowed)
__device__ __align__(16) float g_sk[Bz*Tz*Ez];
__device__ __align__(16) float g_sv[Bz*Tz*Ez];
__device__ __align__(16) float g_nkp[NCTA*Ez];   // per-chunk sum-of-squares (k)
__device__ __align__(16) float g_nvp[NCTA*Ez];   // per-chunk sum-of-squares (v)
__device__ __align__(16) float g_lossp[Bz*Tz];
__device__ __align__(16) float g_part[NCTA*PARTSZ2];
__device__ __align__(16) float g_corr[Bz*PARTSZ2];

// ---------------------------------------------------------------------------
// K1: s_k = silu(x @ WK^T), s_v = silu(x @ WV^T); per-CTA sum-of-squares
// partials (no global atomics, no zero-init kernel needed).
// ---------------------------------------------------------------------------
__global__ __launch_bounds__(256) void k_proj(const float* __restrict__ x,
                                              const float* __restrict__ WK,
                                              const float* __restrict__ WV) {
    __shared__ float sWK[64*65], sWV[64*65], sx[TC*64], sk2[64], sv2[64];
    const int b  = blockIdx.x >> 4;
    const int t0 = (blockIdx.x & 15) * TC;
    const int tid = threadIdx.x;
    for (int i = tid; i < 4096; i += 256) {
        int e = i >> 6, j = i & 63;
        sWK[e*65 + j] = WK[i];
        sWV[e*65 + j] = WV[i];
    }
    for (int i = tid; i < TC*64; i += 256)
        sx[i] = x[(b*Tz + t0)*64 + i];
    if (tid < 64) { sk2[tid] = 0.f; sv2[tid] = 0.f; }
    __syncthreads();

    const int lane = tid & 31, wp = tid >> 5;   // 8 warps, 4 tokens each
    float acc[4][4];
    #pragma unroll
    for (int r = 0; r < 4; r++)
        #pragma unroll
        for (int tt = 0; tt < 4; tt++) acc[r][tt] = 0.f;

    for (int j = 0; j < 64; j += 4) {
        float xv[4][4];
        #pragma unroll
        for (int tt = 0; tt < 4; tt++) {
            float4 q = *(const float4*)&sx[(wp*4 + tt)*64 + j];
            xv[tt][0] = q.x; xv[tt][1] = q.y; xv[tt][2] = q.z; xv[tt][3] = q.w;
        }
        #pragma unroll
        for (int jj = 0; jj < 4; jj++) {
            float wv[4];
            wv[0] = sWK[(lane     )*65 + j + jj];
            wv[1] = sWK[(lane + 32)*65 + j + jj];
            wv[2] = sWV[(lane     )*65 + j + jj];
            wv[3] = sWV[(lane + 32)*65 + j + jj];
            #pragma unroll
            for (int r = 0; r < 4; r++)
                #pragma unroll
                for (int tt = 0; tt < 4; tt++) acc[r][tt] += wv[r] * xv[tt][jj];
        }
    }

    #pragma unroll
    for (int r = 0; r < 4; r++) {
        int e = lane + 32*(r & 1);
        float sq = 0.f;
        #pragma unroll
        for (int tt = 0; tt < 4; tt++) {
            float z = acc[r][tt];
            float s = z / (1.f + __expf(-z));       // silu
            int t = wp*4 + tt;
            if (r < 2) g_sk[(b*Tz + t0 + t)*64 + e] = s;
            else       g_sv[(b*Tz + t0 + t)*64 + e] = s;
            sq += s * s;
        }
        if (r < 2) atomicAdd(&sk2[e], sq);
        else       atomicAdd(&sv2[e], sq);
    }
    __syncthreads();
    if (tid < 64)       g_nkp[blockIdx.x*64 + tid] = sk2[tid];
    else if (tid < 128) g_nvp[blockIdx.x*64 + tid - 64] = sv2[tid - 64];
}

// ---------------------------------------------------------------------------
// K2: heavy kernel. One CTA per (b, 32-token chunk). 256 threads.
// ---------------------------------------------------------------------------
#define SM_FLOATS 35232
__global__ __launch_bounds__(256, 1) void k_main(const float* __restrict__ W1,
                                                 const float* __restrict__ b1,
                                                 const float* __restrict__ W2,
                                                 const float* __restrict__ b2) {
    extern __shared__ float sm[];
    float* sW1  = sm;                 // 128 x pitch65  = 8320
    float* sW2  = sW1 + 8320;         // 64  x pitch129 = 8256
    float* sk   = sW2 + 8256;         // 32x64
    float* sv   = sk  + 2048;         // 32x64
    float* sh   = sv  + 2048;         // 32x128
    float* ss   = sh  + 4096;         // 32x128
    float* sdy  = ss  + 4096;         // 32x64
    float* sdz  = sdy + 2048;         // 32x128
    float* scD  = sdz + 4096;         // 32
    float* scC  = scD + 32;           // 32
    float* sinvk= scC + 32;           // 64
    float* sinvv= sinvk + 64;         // 64
    float* sloss= sinvv + 64;         // 32

    const int b  = blockIdx.x >> 4;
    const int t0 = (blockIdx.x & 15) * TC;
    const int tid = threadIdx.x;
    const int lane = tid & 31, wp = tid >> 5;

    for (int i = tid; i < 8192; i += 256)
        sW1[(i >> 6)*65 + (i & 63)] = W1[b*8192 + i];
    for (int i = tid; i < 8192; i += 256)
        sW2[(i >> 7)*129 + (i & 127)] = W2[b*8192 + i];
    if (tid < 64) {
        float s = 0.f, s2 = 0.f;
        #pragma unroll
        for (int c = 0; c < NC; c++) {
            s  += g_nkp[(b*NC + c)*64 + tid];
            s2 += g_nvp[(b*NC + c)*64 + tid];
        }
        sinvk[tid] = (s  > 0.f) ? rsqrtf(s)  : 0.f;
        sinvv[tid] = (s2 > 0.f) ? rsqrtf(s2) : 0.f;
    }
    if (tid >= 64 && tid < 96) {
        int tl = tid - 64;
        float n1 = (float)(Tz - (t0 + tl));
        scD[tl] = -0.05f * __expf(n1 * LNETA);       // -theta*eta^{n+1}
        scC[tl] = CORRK  * __expf(n1 * LNBETA);      // (theta/(eta-beta))*beta^{n+1}
    }
    __syncthreads();

    for (int i = tid; i < 2048; i += 256) {
        int t = i >> 6, e = i & 63;
        sk[i] = g_sk[(b*Tz + t0 + t)*64 + e] * sinvk[e];
        sv[i] = g_sv[(b*Tz + t0 + t)*64 + e] * sinvv[e];
    }
    __syncthreads();

    // ---- z = W1 k + b1 ; h = silu(z); stash sigmoid ----
    {
        float acc[4][4];
        #pragma unroll
        for (int r = 0; r < 4; r++) {
            float bv = b1[b*128 + lane + 32*r];
            #pragma unroll
            for (int tt = 0; tt < 4; tt++) acc[r][tt] = bv;
        }
        for (int j = 0; j < 64; j += 4) {
            float kv[4][4];
            #pragma unroll
            for (int tt = 0; tt < 4; tt++) {
                float4 q = *(const float4*)&sk[(wp*4 + tt)*64 + j];
                kv[tt][0] = q.x; kv[tt][1] = q.y; kv[tt][2] = q.z; kv[tt][3] = q.w;
            }
            #pragma unroll
            for (int jj = 0; jj < 4; jj++) {
                float wv[4];
                #pragma unroll
                for (int r = 0; r < 4; r++) wv[r] = sW1[(lane + 32*r)*65 + j + jj];
                #pragma unroll
                for (int r = 0; r < 4; r++)
                    #pragma unroll
                    for (int tt = 0; tt < 4; tt++) acc[r][tt] += wv[r] * kv[tt][jj];
            }
        }
        #pragma unroll
        for (int r = 0; r < 4; r++)
            #pragma unroll
            for (int tt = 0; tt < 4; tt++) {
                int idx = (wp*4 + tt)*128 + lane + 32*r;
                float z  = acc[r][tt];
                float sg = 1.f / (1.f + __expf(-z));
                ss[idx] = sg;
                sh[idx] = z * sg;
            }
    }
    __syncthreads();

    // ---- y = W2 h + b2 ; dy = (y - v)/256 ; per-token loss ----
    {
        float acc[2][4];
        #pragma unroll
        for (int r = 0; r < 2; r++) {
            float bv = b2[b*64 + lane + 32*r];
            #pragma unroll
            for (int tt = 0; tt < 4; tt++) acc[r][tt] = bv;
        }
        for (int j = 0; j < 128; j += 4) {
            float hv[4][4];
            #pragma unroll
            for (int tt = 0; tt < 4; tt++) {
                float4 q = *(const float4*)&sh[(wp*4 + tt)*128 + j];
                hv[tt][0] = q.x; hv[tt][1] = q.y; hv[tt][2] = q.z; hv[tt][3] = q.w;
            }
            #pragma unroll
            for (int jj = 0; jj < 4; jj++) {
                float w0 = sW2[(lane     )*129 + j + jj];
                float w1 = sW2[(lane + 32)*129 + j + jj];
                #pragma unroll
                for (int tt = 0; tt < 4; tt++) {
                    acc[0][tt] += w0 * hv[tt][jj];
                    acc[1][tt] += w1 * hv[tt][jj];
                }
            }
        }
        #pragma unroll
        for (int tt = 0; tt < 4; tt++) {
            int t = wp*4 + tt;
            float l = 0.f;
            #pragma unroll
            for (int r = 0; r < 2; r++) {
                int e = lane + 32*r;
                float d = acc[r][tt] - sv[t*64 + e];
                sdy[t*64 + e] = d * (1.f/256.f);
                l += d * d;
            }
            #pragma unroll
            for (int o = 16; o; o >>= 1) l += __shfl_xor_sync(0xffffffffu, l, o);
            if (lane == 0) sloss[t] = l;
        }
    }
    __syncthreads();

    // ---- dh = W2^T dy ; dz = dh * dsilu ----
    {
        float acc[4][4];
        #pragma unroll
        for (int r = 0; r < 4; r++)
            #pragma unroll
            for (int tt = 0; tt < 4; tt++) acc[r][tt] = 0.f;
        for (int e = 0; e < 64; e += 4) {
            float dv[4][4];
            #pragma unroll
            for (int tt = 0; tt < 4; tt++) {
                float4 q = *(const float4*)&sdy[(wp*4 + tt)*64 + e];
                dv[tt][0] = q.x; dv[tt][1] = q.y; dv[tt][2] = q.z; dv[tt][3] = q.w;
            }
            #pragma unroll
            for (int ee = 0; ee < 4; ee++) {
                float wv[4];
                #pragma unroll
                for (int r = 0; r < 4; r++) wv[r] = sW2[(e + ee)*129 + lane + 32*r];
                #pragma unroll
                for (int r = 0; r < 4; r++)
                    #pragma unroll
                    for (int tt = 0; tt < 4; tt++) acc[r][tt] += wv[r] * dv[tt][ee];
            }
        }
        #pragma unroll
        for (int r = 0; r < 4; r++)
            #pragma unroll
            for (int tt = 0; tt < 4; tt++) {
                int idx = (wp*4 + tt)*128 + lane + 32*r;
                float sg = ss[idx], hv = sh[idx];
                sdz[idx] = acc[r][tt] * (sg + hv * (1.f - sg));  // dsilu
            }
    }
    __syncthreads();

    // ---- D-weighted outer-product accumulation (contiguous tiles) ----
    const int e0 = (tid & 15) * 4;   // 4 consecutive e
    const int h0 = (tid >> 4) * 8;   // 8 consecutive h
    float a1[8][4], a2[4][8];
    #pragma unroll
    for (int i = 0; i < 8; i++)
        #pragma unroll
        for (int j = 0; j < 4; j++) { a1[i][j] = 0.f; a2[j][i] = 0.f; }

    for (int t = 0; t < TC; t++) {
        float cd = scD[t];
        float4 kq = *(const float4*)&sk[t*64 + e0];
        float ks[4] = {cd*kq.x, cd*kq.y, cd*kq.z, cd*kq.w};
        float4 z0 = *(const float4*)&sdz[t*128 + h0];
        float4 z1 = *(const float4*)&sdz[t*128 + h0 + 4];
        float dzv[8] = {z0.x, z0.y, z0.z, z0.w, z1.x, z1.y, z1.z, z1.w};
        #pragma unroll
        for (int i = 0; i < 8; i++)
            #pragma unroll
            for (int j = 0; j < 4; j++) a1[i][j] += dzv[i] * ks[j];
        float4 dq = *(const float4*)&sdy[t*64 + e0];
        float dys[4] = {cd*dq.x, cd*dq.y, cd*dq.z, cd*dq.w};
        float4 hq0 = *(const float4*)&sh[t*128 + h0];
        float4 hq1 = *(const float4*)&sh[t*128 + h0 + 4];
        float hv[8] = {hq0.x, hq0.y, hq0.z, hq0.w, hq1.x, hq1.y, hq1.z, hq1.w};
        #pragma unroll
        for (int j = 0; j < 4; j++)
            #pragma unroll
            for (int i = 0; i < 8; i++) a2[j][i] += dys[j] * hv[i];
    }

    float* p = g_part + (size_t)blockIdx.x * PARTSZ2;
    #pragma unroll
    for (int i = 0; i < 8; i++)
        *(float4*)&p[OF2_W1D + (h0 + i)*64 + e0] =
            make_float4(a1[i][0], a1[i][1], a1[i][2], a1[i][3]);
    #pragma unroll
    for (int j = 0; j < 4; j++) {
        *(float4*)&p[OF2_W2D + (e0 + j)*128 + h0] =
            make_float4(a2[j][0], a2[j][1], a2[j][2], a2[j][3]);
        *(float4*)&p[OF2_W2D + (e0 + j)*128 + h0 + 4] =
            make_float4(a2[j][4], a2[j][5], a2[j][6], a2[j][7]);
    }
    if (tid < 128) {
        float aD = 0.f;
        for (int t = 0; t < TC; t++) aD += scD[t] * sdz[t*128 + tid];
        p[OF2_B1D + tid] = aD;
    } else if (tid < 192) {
        int e = tid - 128;
        float aD = 0.f;
        for (int t = 0; t < TC; t++) aD += scD[t] * sdy[t*64 + e];
        p[OF2_B2D + e] = aD;
    }
    if (tid < TC) g_lossp[b*Tz + t0 + tid] = sloss[tid];

    // ---- correction (last chunk only; beta^n support = last ~13 tokens) ----
    if ((blockIdx.x & 15) == 15) {
        #pragma unroll
        for (int i = 0; i < 8; i++)
            #pragma unroll
            for (int j = 0; j < 4; j++) { a1[i][j] = 0.f; a2[j][i] = 0.f; }
        for (int t = 16; t < TC; t++) {
            float cc = scC[t];
            float4 kq = *(const float4*)&sk[t*64 + e0];
            float ks[4] = {cc*kq.x, cc*kq.y, cc*kq.z, cc*kq.w};
            float4 z0 = *(const float4*)&sdz[t*128 + h0];
            float4 z1 = *(const float4*)&sdz[t*128 + h0 + 4];
            float dzv[8] = {z0.x, z0.y, z0.z, z0.w, z1.x, z1.y, z1.z, z1.w};
            #pragma unroll
            for (int i = 0; i < 8; i++)
                #pragma unroll
                for (int j = 0; j < 4; j++) a1[i][j] += dzv[i] * ks[j];
            float4 dq = *(const float4*)&sdy[t*64 + e0];
            float dys[4] = {cc*dq.x, cc*dq.y, cc*dq.z, cc*dq.w};
            float4 hq0 = *(const float4*)&sh[t*128 + h0];
            float4 hq1 = *(const float4*)&sh[t*128 + h0 + 4];
            float hv[8] = {hq0.x, hq0.y, hq0.z, hq0.w, hq1.x, hq1.y, hq1.z, hq1.w};
            #pragma unroll
            for (int j = 0; j < 4; j++)
                #pragma unroll
                for (int i = 0; i < 8; i++) a2[j][i] += dys[j] * hv[i];
        }
        float* q = g_corr + (size_t)b * PARTSZ2;
        #pragma unroll
        for (int i = 0; i < 8; i++)
            *(float4*)&q[OF2_W1D + (h0 + i)*64 + e0] =
                make_float4(a1[i][0], a1[i][1], a1[i][2], a1[i][3]);
        #pragma unroll
        for (int j = 0; j < 4; j++) {
            *(float4*)&q[OF2_W2D + (e0 + j)*128 + h0] =
                make_float4(a2[j][0], a2[j][1], a2[j][2], a2[j][3]);
            *(float4*)&q[OF2_W2D + (e0 + j)*128 + h0 + 4] =
                make_float4(a2[j][4], a2[j][5], a2[j][6], a2[j][7]);
        }
        if (tid < 128) {
            float aC = 0.f;
            for (int t = 16; t < TC; t++) aC += scC[t] * sdz[t*128 + tid];
            q[OF2_B1D + tid] = aC;
        } else if (tid < 192) {
            int e = tid - 128;
            float aC = 0.f;
            for (int t = 16; t < TC; t++) aC += scC[t] * sdy[t*64 + e];
            q[OF2_B2D + e] = aC;
        }
    }
}

// ---------------------------------------------------------------------------
// K3: reduce partials (float4 per thread), apply transforms, write output.
//   gB = rD * INV949 + corr ;  M = aT*S0 + gB (pT=0) ;  S = qT*S0 + rD
// ---------------------------------------------------------------------------
__global__ __launch_bounds__(256) void k_final(const float* __restrict__ SW1,
                                               const float* __restrict__ Sb1,
                                               const float* __restrict__ SW2,
                                               const float* __restrict__ Sb2,
                                               float* __restrict__ out) {
    int i = blockIdx.x * blockDim.x + threadIdx.x;
    const float qT = __expf(-26.262166726f);    // 0.95^512
    const float aT = qT * 1.0010537407f;        // qT/(1-beta/eta)
    if (i < 512) {
        float s = 0.f;
        #pragma unroll
        for (int b = 0; b < Bz; b++) s += g_lossp[b*Tz + i];
        out[O_LOSS + i] = s * (1.f/512.f);
        return;
    }
    int j = i - 512;
    int ofD, nvec_b, segM, segS;
    const float* S0p;
    if (j < 16384) {                 // W1: 2048 vec4 per batch
        ofD = OF2_W1D; nvec_b = 2048; segM = O_MW1; segS = O_SW1; S0p = SW1;
    } else if ((j -= 16384) < 256) { // b1: 32 vec4 per batch
        ofD = OF2_B1D; nvec_b = 32;   segM = O_MB1; segS = O_SB1; S0p = Sb1;
    } else if ((j -= 256) < 16384) { // W2
        ofD = OF2_W2D; nvec_b = 2048; segM = O_MW2; segS = O_SW2; S0p = SW2;
    } else if ((j -= 16384) < 128) { // b2: 16 vec4 per batch
        ofD = OF2_B2D; nvec_b = 16;   segM = O_MB2; segS = O_SB2; S0p = Sb2;
    } else return;

    int b = j / nvec_b;
    int r = (j - b*nvec_b) * 4;
    const float* p = g_part + (size_t)(b*NC) * PARTSZ2 + ofD + r;
    float4 rD = make_float4(0.f, 0.f, 0.f, 0.f);
    #pragma unroll
    for (int c = 0; c < NC; c++) {
        float4 v = *(const float4*)(p + (size_t)c * PARTSZ2);
        rD.x += v.x; rD.y += v.y; rD.z += v.z; rD.w += v.w;
    }
    float4 cr = *(const float4*)(g_corr + (size_t)b * PARTSZ2 + ofD + r);
    int gidx = b * (nvec_b*4) + r;
    float4 s0 = *(const float4*)(S0p + gidx);
    float4 M, S;
    M.x = aT*s0.x + rD.x*INV949 + cr.x;  S.x = qT*s0.x + rD.x;
    M.y = aT*s0.y + rD.y*INV949 + cr.y;  S.y = qT*s0.y + rD.y;
    M.z = aT*s0.z + rD.z*INV949 + cr.z;  S.z = qT*s0.z + rD.z;
    M.w = aT*s0.w + rD.w*INV949 + cr.w;  S.w = qT*s0.w + rD.w;
    *(float4*)(out + segM + gidx) = M;
    *(float4*)(out + segS + gidx) = S;
}

extern "C" void kernel_launch(void* const* d_in, const int* in_sizes, int n_in,
                              void* d_out, int out_size) {
    const float* x   = (const float*)d_in[0];
    const float* WK  = (const float*)d_in[1];
    const float* WV  = (const float*)d_in[2];
    const float* W1  = (const float*)d_in[3];
    const float* b1  = (const float*)d_in[4];
    const float* W2  = (const float*)d_in[5];
    const float* b2  = (const float*)d_in[6];
    const float* SW1 = (const float*)d_in[7];
    const float* Sb1 = (const float*)d_in[8];
    const float* SW2 = (const float*)d_in[9];
    const float* Sb2 = (const float*)d_in[10];
    float* out = (float*)d_out;

    static const size_t smem_main = SM_FLOATS * sizeof(float);
    cudaFuncSetAttribute(k_main, cudaFuncAttributeMaxDynamicSharedMemorySize,
                         (int)smem_main);

    k_proj<<<NCTA, 256>>>(x, WK, WV);
    k_main<<<NCTA, 256, smem_main>>>(W1, b1, W2, b2);
    // threads: 512 loss + 16384 W1 + 256 b1 + 16384 W2 + 128 b2 = 33664
    k_final<<<(33664 + 255) / 256, 256>>>(SW1, Sb1, SW2, Sb2, out);
}

// round 4
// speedup vs baseline: 13.3019x; 1.1750x over previous
#include <cuda_runtime.h>
#include <math.h>

// Problem constants
#define Bz 8
#define Tz 512
#define Ez 64
#define Hz 128
#define TC 32     // tokens per main-kernel CTA
#define NC 16     // chunks per batch (Tz/TC)
#define NCTA (Bz*NC)

// Per-CTA partial layout (floats): D-weighted grads only
#define OF2_W1D 0
#define OF2_B1D 8192
#define OF2_W2D 8320
#define OF2_B2D 16512
#define PARTSZ2 16576

// Output offsets
#define O_LOSS 0
#define O_MW1  512
#define O_MB1  66048
#define O_MW2  67072
#define O_MB2  132608
#define O_SW1  133120
#define O_SB1  198656
#define O_SW2  199680
#define O_SB2  265216

// Coefficient constants: cB[t] = cD[t]*INV949 + corrC[t]
#define LNETA  (-0.0512932943875506f)   // ln(0.95)
#define LNBETA (-6.9077552789821370f)   // ln(0.001)
#define INV949 (1.0537407798735f)       // 1/(0.95-0.001)
#define CORRK  (0.0526870389936f)       // 0.05/0.949

// Scratch (device globals; no allocation allowed)
__device__ __align__(16) float g_sk[Bz*Tz*Ez];
__device__ __align__(16) float g_sv[Bz*Tz*Ez];
__device__ __align__(16) float g_np[256*Ez];    // per-CTA sumsq partials (K then V per b)
__device__ __align__(16) float g_lossp[Bz*Tz];
__device__ __align__(16) float g_part[NCTA*PARTSZ2];
__device__ __align__(16) float g_corr[Bz*PARTSZ2];

// ---------------------------------------------------------------------------
// K1: silu projections. 256 CTAs: bid = b*32 + mat*16 + chunk (32 tokens).
// Each CTA handles ONE matrix (K or V) -> 2x grid parallelism, half the work.
// ---------------------------------------------------------------------------
__global__ __launch_bounds__(256) void k_proj(const float* __restrict__ x,
                                              const float* __restrict__ WK,
                                              const float* __restrict__ WV) {
    __shared__ float sW[64*65], sx[TC*64], sq2[64];
    const int bid  = blockIdx.x;
    const int b    = bid >> 5;
    const int mat  = (bid >> 4) & 1;
    const int t0   = (bid & 15) * TC;
    const int tid  = threadIdx.x;
    const float* W = mat ? WV : WK;
    float* gout    = mat ? g_sv : g_sk;

    for (int i = tid*4; i < 4096; i += 1024) {
        float4 q = *(const float4*)&W[i];
        int e = i >> 6, j = i & 63;
        sW[e*65 + j]     = q.x;
        sW[e*65 + j + 1] = q.y;
        sW[e*65 + j + 2] = q.z;
        sW[e*65 + j + 3] = q.w;
    }
    for (int i = tid*4; i < TC*64; i += 1024)
        *(float4*)&sx[i] = *(const float4*)&x[(b*Tz + t0)*64 + i];
    if (tid < 64) sq2[tid] = 0.f;
    __syncthreads();

    const int lane = tid & 31, wp = tid >> 5;   // 8 warps, 4 tokens each
    float acc[2][4];
    #pragma unroll
    for (int r = 0; r < 2; r++)
        #pragma unroll
        for (int tt = 0; tt < 4; tt++) acc[r][tt] = 0.f;

    for (int j = 0; j < 64; j += 4) {
        float xv[4][4];
        #pragma unroll
        for (int tt = 0; tt < 4; tt++) {
            float4 q = *(const float4*)&sx[(wp*4 + tt)*64 + j];
            xv[tt][0] = q.x; xv[tt][1] = q.y; xv[tt][2] = q.z; xv[tt][3] = q.w;
        }
        #pragma unroll
        for (int jj = 0; jj < 4; jj++) {
            float w0 = sW[(lane     )*65 + j + jj];
            float w1 = sW[(lane + 32)*65 + j + jj];
            #pragma unroll
            for (int tt = 0; tt < 4; tt++) {
                acc[0][tt] += w0 * xv[tt][jj];
                acc[1][tt] += w1 * xv[tt][jj];
            }
        }
    }

    #pragma unroll
    for (int r = 0; r < 2; r++) {
        int e = lane + 32*r;
        float sq = 0.f;
        #pragma unroll
        for (int tt = 0; tt < 4; tt++) {
            float z = acc[r][tt];
            float s = z / (1.f + __expf(-z));       // silu
            gout[(b*Tz + t0 + wp*4 + tt)*64 + e] = s;
            sq += s * s;
        }
        atomicAdd(&sq2[e], sq);
    }
    __syncthreads();
    if (tid < 64) g_np[bid*64 + tid] = sq2[tid];
}

// ---------------------------------------------------------------------------
// K2: heavy kernel. 128 CTAs x 512 threads (16 warps -> 4/SMSP).
// sdy/sdz overlaid into dead sW1 region: smem 113.6KB.
// ---------------------------------------------------------------------------
#define SM_FLOATS 29088
__global__ __launch_bounds__(512, 1) void k_main(const float* __restrict__ W1,
                                                 const float* __restrict__ b1,
                                                 const float* __restrict__ W2,
                                                 const float* __restrict__ b2) {
    extern __shared__ float sm[];
    float* sW1  = sm;                 // 128 x pitch65 = 8320 (phase-z only)
    float* sdy  = sm;                 // 32x64  (overlay, written after z)
    float* sdz  = sm + 2048;          // 32x128 (overlay)
    float* sW2  = sm + 8320;          // 64 x pitch129 = 8256
    float* sk   = sW2 + 8256;         // 32x64
    float* sv   = sk  + 2048;         // 32x64
    float* sh   = sv  + 2048;         // 32x128
    float* ss   = sh  + 4096;         // 32x128
    float* scD  = ss  + 4096;         // 32
    float* scC  = scD + 32;           // 32
    float* sinvk= scC + 32;           // 64
    float* sinvv= sinvk + 64;         // 64
    float* sloss= sinvv + 64;         // 32

    const int b  = blockIdx.x >> 4;
    const int t0 = (blockIdx.x & 15) * TC;
    const int tid = threadIdx.x;
    const int lane = tid & 31, wp = tid >> 5;   // 16 warps, 2 tokens each

    for (int i = tid*4; i < 8192; i += 2048) {
        float4 q = *(const float4*)&W1[b*8192 + i];
        int r = i >> 6, c = i & 63;
        sW1[r*65 + c] = q.x; sW1[r*65 + c+1] = q.y;
        sW1[r*65 + c+2] = q.z; sW1[r*65 + c+3] = q.w;
    }
    for (int i = tid*4; i < 8192; i += 2048) {
        float4 q = *(const float4*)&W2[b*8192 + i];
        int r = i >> 7, c = i & 127;
        sW2[r*129 + c] = q.x; sW2[r*129 + c+1] = q.y;
        sW2[r*129 + c+2] = q.z; sW2[r*129 + c+3] = q.w;
    }
    if (tid < 64) {
        float s = 0.f, s2 = 0.f;
        #pragma unroll
        for (int c = 0; c < NC; c++) {
            s  += g_np[(b*32 + c)*64 + tid];
            s2 += g_np[(b*32 + 16 + c)*64 + tid];
        }
        sinvk[tid] = (s  > 0.f) ? rsqrtf(s)  : 0.f;
        sinvv[tid] = (s2 > 0.f) ? rsqrtf(s2) : 0.f;
    }
    if (tid >= 64 && tid < 96) {
        int tl = tid - 64;
        float n1 = (float)(Tz - (t0 + tl));
        scD[tl] = -0.05f * __expf(n1 * LNETA);
        scC[tl] = CORRK  * __expf(n1 * LNBETA);
    }
    __syncthreads();

    // normalize + stage k, v (float4)
    for (int idx = tid; idx < 512; idx += 512) {
        int t = idx >> 4, e4 = (idx & 15) * 4;
        float4 q = *(const float4*)&g_sk[(b*Tz + t0 + t)*64 + e4];
        q.x *= sinvk[e4]; q.y *= sinvk[e4+1]; q.z *= sinvk[e4+2]; q.w *= sinvk[e4+3];
        *(float4*)&sk[t*64 + e4] = q;
        float4 p = *(const float4*)&g_sv[(b*Tz + t0 + t)*64 + e4];
        p.x *= sinvv[e4]; p.y *= sinvv[e4+1]; p.z *= sinvv[e4+2]; p.w *= sinvv[e4+3];
        *(float4*)&sv[t*64 + e4] = p;
    }
    __syncthreads();

    // ---- z = W1 k + b1 ; h = silu(z); stash sigmoid ----
    {
        float acc[4][2];
        #pragma unroll
        for (int r = 0; r < 4; r++) {
            float bv = b1[b*128 + lane + 32*r];
            acc[r][0] = bv; acc[r][1] = bv;
        }
        for (int j = 0; j < 64; j += 4) {
            float kv[2][4];
            #pragma unroll
            for (int tt = 0; tt < 2; tt++) {
                float4 q = *(const float4*)&sk[(wp*2 + tt)*64 + j];
                kv[tt][0] = q.x; kv[tt][1] = q.y; kv[tt][2] = q.z; kv[tt][3] = q.w;
            }
            #pragma unroll
            for (int jj = 0; jj < 4; jj++) {
                float wv[4];
                #pragma unroll
                for (int r = 0; r < 4; r++) wv[r] = sW1[(lane + 32*r)*65 + j + jj];
                #pragma unroll
                for (int r = 0; r < 4; r++)
                    #pragma unroll
                    for (int tt = 0; tt < 2; tt++) acc[r][tt] += wv[r] * kv[tt][jj];
            }
        }
        #pragma unroll
        for (int r = 0; r < 4; r++)
            #pragma unroll
            for (int tt = 0; tt < 2; tt++) {
                int idx = (wp*2 + tt)*128 + lane + 32*r;
                float z  = acc[r][tt];
                float sg = 1.f / (1.f + __expf(-z));
                ss[idx] = sg;
                sh[idx] = z * sg;
            }
    }
    __syncthreads();   // sW1 dead; sdy/sdz overlay valid from here

    // ---- y = W2 h + b2 ; dy = (y - v)/256 ; per-token loss ----
    {
        float acc[2][2];
        #pragma unroll
        for (int r = 0; r < 2; r++) {
            float bv = b2[b*64 + lane + 32*r];
            acc[r][0] = bv; acc[r][1] = bv;
        }
        for (int j = 0; j < 128; j += 4) {
            float hv[2][4];
            #pragma unroll
            for (int tt = 0; tt < 2; tt++) {
                float4 q = *(const float4*)&sh[(wp*2 + tt)*128 + j];
                hv[tt][0] = q.x; hv[tt][1] = q.y; hv[tt][2] = q.z; hv[tt][3] = q.w;
            }
            #pragma unroll
            for (int jj = 0; jj < 4; jj++) {
                float w0 = sW2[(lane     )*129 + j + jj];
                float w1 = sW2[(lane + 32)*129 + j + jj];
                #pragma unroll
                for (int tt = 0; tt < 2; tt++) {
                    acc[0][tt] += w0 * hv[tt][jj];
                    acc[1][tt] += w1 * hv[tt][jj];
                }
            }
        }
        #pragma unroll
        for (int tt = 0; tt < 2; tt++) {
            int t = wp*2 + tt;
            float l = 0.f;
            #pragma unroll
            for (int r = 0; r < 2; r++) {
                int e = lane + 32*r;
                float d = acc[r][tt] - sv[t*64 + e];
                sdy[t*64 + e] = d * (1.f/256.f);
                l += d * d;
            }
            #pragma unroll
            for (int o = 16; o; o >>= 1) l += __shfl_xor_sync(0xffffffffu, l, o);
            if (lane == 0) sloss[t] = l;
        }
    }
    __syncthreads();

    // ---- dh = W2^T dy ; dz = dh * dsilu ----
    {
        float acc[4][2];
        #pragma unroll
        for (int r = 0; r < 4; r++) { acc[r][0] = 0.f; acc[r][1] = 0.f; }
        for (int e = 0; e < 64; e += 4) {
            float dv[2][4];
            #pragma unroll
            for (int tt = 0; tt < 2; tt++) {
                float4 q = *(const float4*)&sdy[(wp*2 + tt)*64 + e];
                dv[tt][0] = q.x; dv[tt][1] = q.y; dv[tt][2] = q.z; dv[tt][3] = q.w;
            }
            #pragma unroll
            for (int ee = 0; ee < 4; ee++) {
                float wv[4];
                #pragma unroll
                for (int r = 0; r < 4; r++) wv[r] = sW2[(e + ee)*129 + lane + 32*r];
                #pragma unroll
                for (int r = 0; r < 4; r++)
                    #pragma unroll
                    for (int tt = 0; tt < 2; tt++) acc[r][tt] += wv[r] * dv[tt][ee];
            }
        }
        #pragma unroll
        for (int r = 0; r < 4; r++)
            #pragma unroll
            for (int tt = 0; tt < 2; tt++) {
                int idx = (wp*2 + tt)*128 + lane + 32*r;
                float sg = ss[idx], hv = sh[idx];
                sdz[idx] = acc[r][tt] * (sg + hv * (1.f - sg));
            }
    }
    __syncthreads();

    // ---- D-weighted outer products: 4e x 4h tile per thread ----
    const int e0 = (tid & 15) * 4;
    const int h0 = (tid >> 4) * 4;
    float a1[4][4], a2[4][4];
    #pragma unroll
    for (int i = 0; i < 4; i++)
        #pragma unroll
        for (int j = 0; j < 4; j++) { a1[i][j] = 0.f; a2[j][i] = 0.f; }

    for (int t = 0; t < TC; t++) {
        float cd = scD[t];
        float4 kq = *(const float4*)&sk[t*64 + e0];
        float ks[4] = {cd*kq.x, cd*kq.y, cd*kq.z, cd*kq.w};
        float4 zq = *(const float4*)&sdz[t*128 + h0];
        float dzv[4] = {zq.x, zq.y, zq.z, zq.w};
        #pragma unroll
        for (int i = 0; i < 4; i++)
            #pragma unroll
            for (int j = 0; j < 4; j++) a1[i][j] += dzv[i] * ks[j];
        float4 dq = *(const float4*)&sdy[t*64 + e0];
        float dys[4] = {cd*dq.x, cd*dq.y, cd*dq.z, cd*dq.w};
        float4 hq = *(const float4*)&sh[t*128 + h0];
        float hv[4] = {hq.x, hq.y, hq.z, hq.w};
        #pragma unroll
        for (int j = 0; j < 4; j++)
            #pragma unroll
            for (int i = 0; i < 4; i++) a2[j][i] += dys[j] * hv[i];
    }

    float* p = g_part + (size_t)blockIdx.x * PARTSZ2;
    #pragma unroll
    for (int i = 0; i < 4; i++)
        *(float4*)&p[OF2_W1D + (h0 + i)*64 + e0] =
            make_float4(a1[i][0], a1[i][1], a1[i][2], a1[i][3]);
    #pragma unroll
    for (int j = 0; j < 4; j++)
        *(float4*)&p[OF2_W2D + (e0 + j)*128 + h0] =
            make_float4(a2[j][0], a2[j][1], a2[j][2], a2[j][3]);
    if (tid < 128) {
        float aD = 0.f;
        for (int t = 0; t < TC; t++) aD += scD[t] * sdz[t*128 + tid];
        p[OF2_B1D + tid] = aD;
    } else if (tid < 192) {
        int e = tid - 128;
        float aD = 0.f;
        for (int t = 0; t < TC; t++) aD += scD[t] * sdy[t*64 + e];
        p[OF2_B2D + e] = aD;
    }
    if (tid < TC) g_lossp[b*Tz + t0 + tid] = sloss[tid];

    // ---- correction (last chunk only; beta^n support ~ last 13 tokens) ----
    if ((blockIdx.x & 15) == 15) {
        #pragma unroll
        for (int i = 0; i < 4; i++)
            #pragma unroll
            for (int j = 0; j < 4; j++) { a1[i][j] = 0.f; a2[j][i] = 0.f; }
        for (int t = 16; t < TC; t++) {
            float cc = scC[t];
            float4 kq = *(const float4*)&sk[t*64 + e0];
            float ks[4] = {cc*kq.x, cc*kq.y, cc*kq.z, cc*kq.w};
            float4 zq = *(const float4*)&sdz[t*128 + h0];
            float dzv[4] = {zq.x, zq.y, zq.z, zq.w};
            #pragma unroll
            for (int i = 0; i < 4; i++)
                #pragma unroll
                for (int j = 0; j < 4; j++) a1[i][j] += dzv[i] * ks[j];
            float4 dq = *(const float4*)&sdy[t*64 + e0];
            float dys[4] = {cc*dq.x, cc*dq.y, cc*dq.z, cc*dq.w};
            float4 hq = *(const float4*)&sh[t*128 + h0];
            float hv[4] = {hq.x, hq.y, hq.z, hq.w};
            #pragma unroll
            for (int j = 0; j < 4; j++)
                #pragma unroll
                for (int i = 0; i < 4; i++) a2[j][i] += dys[j] * hv[i];
        }
        float* q = g_corr + (size_t)b * PARTSZ2;
        #pragma unroll
        for (int i = 0; i < 4; i++)
            *(float4*)&q[OF2_W1D + (h0 + i)*64 + e0] =
                make_float4(a1[i][0], a1[i][1], a1[i][2], a1[i][3]);
        #pragma unroll
        for (int j = 0; j < 4; j++)
            *(float4*)&q[OF2_W2D + (e0 + j)*128 + h0] =
                make_float4(a2[j][0], a2[j][1], a2[j][2], a2[j][3]);
        if (tid < 128) {
            float aC = 0.f;
            for (int t = 16; t < TC; t++) aC += scC[t] * sdz[t*128 + tid];
            q[OF2_B1D + tid] = aC;
        } else if (tid < 192) {
            int e = tid - 128;
            float aC = 0.f;
            for (int t = 16; t < TC; t++) aC += scC[t] * sdy[t*64 + e];
            q[OF2_B2D + e] = aC;
        }
    }
}

// ---------------------------------------------------------------------------
// K3: reduce partials (float4/thread), apply transforms, write output.
// ---------------------------------------------------------------------------
__global__ __launch_bounds__(256) void k_final(const float* __restrict__ SW1,
                                               const float* __restrict__ Sb1,
                                               const float* __restrict__ SW2,
                                               const float* __restrict__ Sb2,
                                               float* __restrict__ out) {
    int i = blockIdx.x * blockDim.x + threadIdx.x;
    const float qT = __expf(-26.262166726f);    // 0.95^512
    const float aT = qT * 1.0010537407f;        // qT/(1-beta/eta)
    if (i < 512) {
        float s = 0.f;
        #pragma unroll
        for (int b = 0; b < Bz; b++) s += g_lossp[b*Tz + i];
        out[O_LOSS + i] = s * (1.f/512.f);
        return;
    }
    int j = i - 512;
    int ofD, nvec_b, segM, segS;
    const float* S0p;
    if (j < 16384) {
        ofD = OF2_W1D; nvec_b = 2048; segM = O_MW1; segS = O_SW1; S0p = SW1;
    } else if ((j -= 16384) < 256) {
        ofD = OF2_B1D; nvec_b = 32;   segM = O_MB1; segS = O_SB1; S0p = Sb1;
    } else if ((j -= 256) < 16384) {
        ofD = OF2_W2D; nvec_b = 2048; segM = O_MW2; segS = O_SW2; S0p = SW2;
    } else if ((j -= 16384) < 128) {
        ofD = OF2_B2D; nvec_b = 16;   segM = O_MB2; segS = O_SB2; S0p = Sb2;
    } else return;

    int b = j / nvec_b;
    int r = (j - b*nvec_b) * 4;
    const float* p = g_part + (size_t)(b*NC) * PARTSZ2 + ofD + r;
    float4 rD = make_float4(0.f, 0.f, 0.f, 0.f);
    #pragma unroll
    for (int c = 0; c < NC; c++) {
        float4 v = *(const float4*)(p + (size_t)c * PARTSZ2);
        rD.x += v.x; rD.y += v.y; rD.z += v.z; rD.w += v.w;
    }
    float4 cr = *(const float4*)(g_corr + (size_t)b * PARTSZ2 + ofD + r);
    int gidx = b * (nvec_b*4) + r;
    float4 s0 = *(const float4*)(S0p + gidx);
    float4 M, S;
    M.x = aT*s0.x + rD.x*INV949 + cr.x;  S.x = qT*s0.x + rD.x;
    M.y = aT*s0.y + rD.y*INV949 + cr.y;  S.y = qT*s0.y + rD.y;
    M.z = aT*s0.z + rD.z*INV949 + cr.z;  S.z = qT*s0.z + rD.z;
    M.w = aT*s0.w + rD.w*INV949 + cr.w;  S.w = qT*s0.w + rD.w;
    *(float4*)(out + segM + gidx) = M;
    *(float4*)(out + segS + gidx) = S;
}

extern "C" void kernel_launch(void* const* d_in, const int* in_sizes, int n_in,
                              void* d_out, int out_size) {
    const float* x   = (const float*)d_in[0];
    const float* WK  = (const float*)d_in[1];
    const float* WV  = (const float*)d_in[2];
    const float* W1  = (const float*)d_in[3];
    const float* b1  = (const float*)d_in[4];
    const float* W2  = (const float*)d_in[5];
    const float* b2  = (const float*)d_in[6];
    const float* SW1 = (const float*)d_in[7];
    const float* Sb1 = (const float*)d_in[8];
    const float* SW2 = (const float*)d_in[9];
    const float* Sb2 = (const float*)d_in[10];
    float* out = (float*)d_out;

    static const size_t smem_main = SM_FLOATS * sizeof(float);
    cudaFuncSetAttribute(k_main, cudaFuncAttributeMaxDynamicSharedMemorySize,
                         (int)smem_main);

    k_proj<<<256, 256>>>(x, WK, WV);
    k_main<<<NCTA, 512, smem_main>>>(W1, b1, W2, b2);
    k_final<<<(33664 + 255) / 256, 256>>>(SW1, Sb1, SW2, Sb2, out);
}

// round 6
// speedup vs baseline: 14.0000x; 1.0525x over previous
#include <cuda_runtime.h>
#include <math.h>

// Problem constants
#define Bz 8
#define Tz 512
#define Ez 64
#define Hz 128
#define TC 32     // tokens per main-kernel CTA
#define NC 16     // chunks per batch (Tz/TC)
#define NCTA (Bz*NC)

// Weight pitches (float4-aligned; pitch mod 32 == 4 -> conflict-free LDS.128)
#define P1 68     // sW1 / sWK / sWV pitch
#define P2 132    // sW2 pitch

// Per-CTA partial layout (floats): D-weighted grads only
#define OF2_W1D 0
#define OF2_B1D 8192
#define OF2_W2D 8320
#define OF2_B2D 16512
#define PARTSZ2 16576

// Output offsets
#define O_LOSS 0
#define O_MW1  512
#define O_MB1  66048
#define O_MW2  67072
#define O_MB2  132608
#define O_SW1  133120
#define O_SB1  198656
#define O_SW2  199680
#define O_SB2  265216

// Coefficient constants: cB[t] = cD[t]*INV949 + corrC[t]
#define LNETA  (-0.0512932943875506f)   // ln(0.95)
#define LNBETA (-6.9077552789821370f)   // ln(0.001)
#define INV949 (1.0537407798735f)       // 1/(0.95-0.001)
#define CORRK  (0.0526870389936f)       // 0.05/0.949

// Scratch (device globals; no allocation allowed)
__device__ __align__(16) float g_np[2*NCTA*Ez];  // sumsq partials: K then V
__device__ __align__(16) float g_lossp[Bz*Tz];
__device__ __align__(16) float g_part[NCTA*PARTSZ2];
__device__ __align__(16) float g_corr[Bz*PARTSZ2];
__device__ unsigned g_count;                     // barrier arrive counter (self-resetting)
__device__ volatile unsigned g_phase;            // barrier phase (monotonic across replays)

// ---------------------------------------------------------------------------
// Fused kernel: projections + norm barrier + fwd/bwd + weighted outer products.
// 128 CTAs x 512 threads, all co-resident (118.8KB smem -> 1 CTA/SM).
// ---------------------------------------------------------------------------
#define SM_FLOATS 29696   // >= 29664 actually used (R5 bug: was 29600 -> OOB)
__global__ __launch_bounds__(512, 1) void k_main(const float* __restrict__ x,
                                                 const float* __restrict__ WK,
                                                 const float* __restrict__ WV,
                                                 const float* __restrict__ W1,
                                                 const float* __restrict__ b1,
                                                 const float* __restrict__ W2,
                                                 const float* __restrict__ b2) {
    extern __shared__ float sm[];
    // Region A (8704): phase0 = WK|WV ; phase1 = W1 ; phase2+ = sdy|sdz
    float* sWK  = sm;                 // 64 x P1 = 4352
    float* sWV  = sm + 4352;          // 64 x P1
    float* sW1  = sm;                 // 128 x P1 = 8704
    float* sdy  = sm;                 // 32x64 overlay
    float* sdz  = sm + 2048;          // 32x128 overlay
    // Region B (8448): phase0 = x chunk ; phase1+ = W2
    float* sx   = sm + 8704;          // 32x64 = 2048 (phase0 only)
    float* sW2  = sm + 8704;          // 64 x P2 = 8448
    float* sk   = sm + 17152;         // 32x64
    float* sv   = sk  + 2048;         // 32x64
    float* sh   = sv  + 2048;         // 32x128
    float* ss   = sh  + 4096;         // 32x128
    float* scD  = ss  + 4096;         // 32
    float* scC  = scD + 32;           // 32
    float* sinvk= scC + 32;           // 64 (phase0: K sumsq accum)
    float* sinvv= sinvk + 64;         // 64 (phase0: V sumsq accum)
    float* sloss= sinvv + 64;         // 32   -> total 29664 <= SM_FLOATS

    const int bid = blockIdx.x;
    const int b   = bid >> 4;
    const int t0  = (bid & 15) * TC;
    const int tid = threadIdx.x;
    const int lane = tid & 31, wp = tid >> 5;   // 16 warps, 2 tokens each

    // ---- phase 0 loads: WK, WV (pitched), x chunk ----
    #pragma unroll
    for (int i = tid*4; i < 4096; i += 2048) {
        int e = i >> 6, j = i & 63;
        float4 qk = *(const float4*)&WK[i];
        *(float4*)&sWK[e*P1 + j] = qk;
        float4 qv = *(const float4*)&WV[i];
        *(float4*)&sWV[e*P1 + j] = qv;
    }
    {
        int i = tid*4;
        *(float4*)&sx[i] = *(const float4*)&x[(b*Tz + t0)*64 + i];
    }
    if (tid < 64)       sinvk[tid] = 0.f;
    else if (tid < 128) sinvv[tid - 64] = 0.f;
    if (tid >= 128 && tid < 160) {
        int tl = tid - 128;
        float n1 = (float)(Tz - (t0 + tl));
        scD[tl] = -0.05f * __expf(n1 * LNETA);
        scC[tl] = CORRK  * __expf(n1 * LNBETA);
    }
    __syncthreads();

    // ---- phase 0: s_k = silu(x WK^T), s_v = silu(x WV^T) into smem ----
    {
        float acc[4][2];
        #pragma unroll
        for (int r = 0; r < 4; r++) { acc[r][0] = 0.f; acc[r][1] = 0.f; }
        for (int j = 0; j < 64; j += 4) {
            float xv[2][4];
            #pragma unroll
            for (int tt = 0; tt < 2; tt++) {
                float4 q = *(const float4*)&sx[(wp*2 + tt)*64 + j];
                xv[tt][0] = q.x; xv[tt][1] = q.y; xv[tt][2] = q.z; xv[tt][3] = q.w;
            }
            float4 w4[4];
            w4[0] = *(const float4*)&sWK[(lane     )*P1 + j];
            w4[1] = *(const float4*)&sWK[(lane + 32)*P1 + j];
            w4[2] = *(const float4*)&sWV[(lane     )*P1 + j];
            w4[3] = *(const float4*)&sWV[(lane + 32)*P1 + j];
            #pragma unroll
            for (int r = 0; r < 4; r++) {
                const float* w = (const float*)&w4[r];
                #pragma unroll
                for (int jj = 0; jj < 4; jj++) {
                    acc[r][0] += w[jj] * xv[0][jj];
                    acc[r][1] += w[jj] * xv[1][jj];
                }
            }
        }
        #pragma unroll
        for (int r = 0; r < 4; r++) {
            int e = lane + 32*(r & 1);
            float sq = 0.f;
            #pragma unroll
            for (int tt = 0; tt < 2; tt++) {
                float z = acc[r][tt];
                float s = z / (1.f + __expf(-z));       // silu
                int t = wp*2 + tt;
                if (r < 2) sk[t*64 + e] = s;
                else       sv[t*64 + e] = s;
                sq += s * s;
            }
            if (r < 2) atomicAdd(&sinvk[e], sq);
            else       atomicAdd(&sinvv[e], sq);
        }
    }
    __syncthreads();

    // ---- publish norm partials, global barrier; load W1/W2 meanwhile ----
    if (tid < 64)       g_np[bid*64 + tid] = sinvk[tid];
    else if (tid < 128) g_np[(NCTA + bid)*64 + tid - 64] = sinvv[tid - 64];
    __threadfence();
    __syncthreads();
    if (tid == 0) {
        unsigned my = g_phase;
        unsigned old = atomicAdd(&g_count, 1);
        if (old == NCTA - 1) {
            g_count = 0;
            __threadfence();
            atomicAdd((unsigned*)&g_phase, 1);
        } else {
            while (g_phase == my) { }
        }
        __threadfence();
    }
    // overlap: load W1/W2 (WK/WV/x dead after phase0 sync)
    #pragma unroll
    for (int i = tid*4; i < 8192; i += 2048) {
        float4 q = *(const float4*)&W1[b*8192 + i];
        *(float4*)&sW1[(i >> 6)*P1 + (i & 63)] = q;
    }
    #pragma unroll
    for (int i = tid*4; i < 8192; i += 2048) {
        float4 q = *(const float4*)&W2[b*8192 + i];
        *(float4*)&sW2[(i >> 7)*P2 + (i & 127)] = q;
    }
    __syncthreads();   // tid0 holds everyone until global barrier passed

    // ---- reduce norms, write inverse norms ----
    if (tid < 64) {
        float s = 0.f, s2 = 0.f;
        #pragma unroll
        for (int c = 0; c < NC; c++) {
            s  += g_np[(b*NC + c)*64 + tid];
            s2 += g_np[(NCTA + b*NC + c)*64 + tid];
        }
        sinvk[tid] = (s  > 0.f) ? rsqrtf(s)  : 0.f;
        sinvv[tid] = (s2 > 0.f) ? rsqrtf(s2) : 0.f;
    }
    __syncthreads();

    // ---- normalize k, v in place ----
    {
        int t = tid >> 4, e4 = (tid & 15) * 4;
        float4 q = *(const float4*)&sk[t*64 + e4];
        q.x *= sinvk[e4]; q.y *= sinvk[e4+1]; q.z *= sinvk[e4+2]; q.w *= sinvk[e4+3];
        *(float4*)&sk[t*64 + e4] = q;
        float4 p = *(const float4*)&sv[t*64 + e4];
        p.x *= sinvv[e4]; p.y *= sinvv[e4+1]; p.z *= sinvv[e4+2]; p.w *= sinvv[e4+3];
        *(float4*)&sv[t*64 + e4] = p;
    }
    __syncthreads();

    // ---- z = W1 k + b1 ; h = silu(z); stash sigmoid ----
    {
        float acc[4][2];
        #pragma unroll
        for (int r = 0; r < 4; r++) {
            float bv = b1[b*128 + lane + 32*r];
            acc[r][0] = bv; acc[r][1] = bv;
        }
        for (int j = 0; j < 64; j += 4) {
            float kv[2][4];
            #pragma unroll
            for (int tt = 0; tt < 2; tt++) {
                float4 q = *(const float4*)&sk[(wp*2 + tt)*64 + j];
                kv[tt][0] = q.x; kv[tt][1] = q.y; kv[tt][2] = q.z; kv[tt][3] = q.w;
            }
            float4 w4[4];
            #pragma unroll
            for (int r = 0; r < 4; r++)
                w4[r] = *(const float4*)&sW1[(lane + 32*r)*P1 + j];
            #pragma unroll
            for (int r = 0; r < 4; r++) {
                const float* w = (const float*)&w4[r];
                #pragma unroll
                for (int jj = 0; jj < 4; jj++) {
                    acc[r][0] += w[jj] * kv[0][jj];
                    acc[r][1] += w[jj] * kv[1][jj];
                }
            }
        }
        #pragma unroll
        for (int r = 0; r < 4; r++)
            #pragma unroll
            for (int tt = 0; tt < 2; tt++) {
                int idx = (wp*2 + tt)*128 + lane + 32*r;
                float z  = acc[r][tt];
                float sg = 1.f / (1.f + __expf(-z));
                ss[idx] = sg;
                sh[idx] = z * sg;
            }
    }
    __syncthreads();   // sW1 dead; sdy/sdz overlay valid from here

    // ---- y = W2 h + b2 ; dy = (y - v)/256 ; per-token loss ----
    {
        float acc[2][2];
        #pragma unroll
        for (int r = 0; r < 2; r++) {
            float bv = b2[b*64 + lane + 32*r];
            acc[r][0] = bv; acc[r][1] = bv;
        }
        for (int j = 0; j < 128; j += 4) {
            float hv[2][4];
            #pragma unroll
            for (int tt = 0; tt < 2; tt++) {
                float4 q = *(const float4*)&sh[(wp*2 + tt)*128 + j];
                hv[tt][0] = q.x; hv[tt][1] = q.y; hv[tt][2] = q.z; hv[tt][3] = q.w;
            }
            float4 w40 = *(const float4*)&sW2[(lane     )*P2 + j];
            float4 w41 = *(const float4*)&sW2[(lane + 32)*P2 + j];
            const float* w0 = (const float*)&w40;
            const float* w1 = (const float*)&w41;
            #pragma unroll
            for (int jj = 0; jj < 4; jj++) {
                acc[0][0] += w0[jj] * hv[0][jj];
                acc[0][1] += w0[jj] * hv[1][jj];
                acc[1][0] += w1[jj] * hv[0][jj];
                acc[1][1] += w1[jj] * hv[1][jj];
            }
        }
        #pragma unroll
        for (int tt = 0; tt < 2; tt++) {
            int t = wp*2 + tt;
            float l = 0.f;
            #pragma unroll
            for (int r = 0; r < 2; r++) {
                int e = lane + 32*r;
                float d = acc[r][tt] - sv[t*64 + e];
                sdy[t*64 + e] = d * (1.f/256.f);
                l += d * d;
            }
            #pragma unroll
            for (int o = 16; o; o >>= 1) l += __shfl_xor_sync(0xffffffffu, l, o);
            if (lane == 0) sloss[t] = l;
        }
    }
    __syncthreads();

    // ---- dh = W2^T dy ; dz = dh * dsilu ----
    {
        float acc[4][2];
        #pragma unroll
        for (int r = 0; r < 4; r++) { acc[r][0] = 0.f; acc[r][1] = 0.f; }
        for (int e = 0; e < 64; e += 4) {
            float dv[2][4];
            #pragma unroll
            for (int tt = 0; tt < 2; tt++) {
                float4 q = *(const float4*)&sdy[(wp*2 + tt)*64 + e];
                dv[tt][0] = q.x; dv[tt][1] = q.y; dv[tt][2] = q.z; dv[tt][3] = q.w;
            }
            #pragma unroll
            for (int ee = 0; ee < 4; ee++) {
                float wv[4];
                #pragma unroll
                for (int r = 0; r < 4; r++) wv[r] = sW2[(e + ee)*P2 + lane + 32*r];
                #pragma unroll
                for (int r = 0; r < 4; r++) {
                    acc[r][0] += wv[r] * dv[0][ee];
                    acc[r][1] += wv[r] * dv[1][ee];
                }
            }
        }
        #pragma unroll
        for (int r = 0; r < 4; r++)
            #pragma unroll
            for (int tt = 0; tt < 2; tt++) {
                int idx = (wp*2 + tt)*128 + lane + 32*r;
                float sg = ss[idx], hv = sh[idx];
                sdz[idx] = acc[r][tt] * (sg + hv * (1.f - sg));
            }
    }
    __syncthreads();

    // ---- D-weighted outer products: 4e x 4h tile per thread ----
    const int e0 = (tid & 15) * 4;
    const int h0 = (tid >> 4) * 4;
    float a1[4][4], a2[4][4];
    #pragma unroll
    for (int i = 0; i < 4; i++)
        #pragma unroll
        for (int j = 0; j < 4; j++) { a1[i][j] = 0.f; a2[j][i] = 0.f; }

    for (int t = 0; t < TC; t++) {
        float cd = scD[t];
        float4 kq = *(const float4*)&sk[t*64 + e0];
        float ks[4] = {cd*kq.x, cd*kq.y, cd*kq.z, cd*kq.w};
        float4 zq = *(const float4*)&sdz[t*128 + h0];
        float dzv[4] = {zq.x, zq.y, zq.z, zq.w};
        #pragma unroll
        for (int i = 0; i < 4; i++)
            #pragma unroll
            for (int j = 0; j < 4; j++) a1[i][j] += dzv[i] * ks[j];
        float4 dq = *(const float4*)&sdy[t*64 + e0];
        float dys[4] = {cd*dq.x, cd*dq.y, cd*dq.z, cd*dq.w};
        float4 hq = *(const float4*)&sh[t*128 + h0];
        float hv[4] = {hq.x, hq.y, hq.z, hq.w};
        #pragma unroll
        for (int j = 0; j < 4; j++)
            #pragma unroll
            for (int i = 0; i < 4; i++) a2[j][i] += dys[j] * hv[i];
    }

    float* p = g_part + (size_t)bid * PARTSZ2;
    #pragma unroll
    for (int i = 0; i < 4; i++)
        *(float4*)&p[OF2_W1D + (h0 + i)*64 + e0] =
            make_float4(a1[i][0], a1[i][1], a1[i][2], a1[i][3]);
    #pragma unroll
    for (int j = 0; j < 4; j++)
        *(float4*)&p[OF2_W2D + (e0 + j)*128 + h0] =
            make_float4(a2[j][0], a2[j][1], a2[j][2], a2[j][3]);
    if (tid < 128) {
        float aD = 0.f;
        for (int t = 0; t < TC; t++) aD += scD[t] * sdz[t*128 + tid];
        p[OF2_B1D + tid] = aD;
    } else if (tid < 192) {
        int e = tid - 128;
        float aD = 0.f;
        for (int t = 0; t < TC; t++) aD += scD[t] * sdy[t*64 + e];
        p[OF2_B2D + e] = aD;
    }
    if (tid < TC) g_lossp[b*Tz + t0 + tid] = sloss[tid];

    // ---- correction (last chunk only; beta^n support ~ last 13 tokens) ----
    if ((bid & 15) == 15) {
        #pragma unroll
        for (int i = 0; i < 4; i++)
            #pragma unroll
            for (int j = 0; j < 4; j++) { a1[i][j] = 0.f; a2[j][i] = 0.f; }
        for (int t = 16; t < TC; t++) {
            float cc = scC[t];
            float4 kq = *(const float4*)&sk[t*64 + e0];
            float ks[4] = {cc*kq.x, cc*kq.y, cc*kq.z, cc*kq.w};
            float4 zq = *(const float4*)&sdz[t*128 + h0];
            float dzv[4] = {zq.x, zq.y, zq.z, zq.w};
            #pragma unroll
            for (int i = 0; i < 4; i++)
                #pragma unroll
                for (int j = 0; j < 4; j++) a1[i][j] += dzv[i] * ks[j];
            float4 dq = *(const float4*)&sdy[t*64 + e0];
            float dys[4] = {cc*dq.x, cc*dq.y, cc*dq.z, cc*dq.w};
            float4 hq = *(const float4*)&sh[t*128 + h0];
            float hv[4] = {hq.x, hq.y, hq.z, hq.w};
            #pragma unroll
            for (int j = 0; j < 4; j++)
                #pragma unroll
                for (int i = 0; i < 4; i++) a2[j][i] += dys[j] * hv[i];
        }
        float* q = g_corr + (size_t)b * PARTSZ2;
        #pragma unroll
        for (int i = 0; i < 4; i++)
            *(float4*)&q[OF2_W1D + (h0 + i)*64 + e0] =
                make_float4(a1[i][0], a1[i][1], a1[i][2], a1[i][3]);
        #pragma unroll
        for (int j = 0; j < 4; j++)
            *(float4*)&q[OF2_W2D + (e0 + j)*128 + h0] =
                make_float4(a2[j][0], a2[j][1], a2[j][2], a2[j][3]);
        if (tid < 128) {
            float aC = 0.f;
            for (int t = 16; t < TC; t++) aC += scC[t] * sdz[t*128 + tid];
            q[OF2_B1D + tid] = aC;
        } else if (tid < 192) {
            int e = tid - 128;
            float aC = 0.f;
            for (int t = 16; t < TC; t++) aC += scC[t] * sdy[t*64 + e];
            q[OF2_B2D + e] = aC;
        }
    }
}

// ---------------------------------------------------------------------------
// K3: reduce partials (float4/thread), apply transforms, write output.
// ---------------------------------------------------------------------------
__global__ __launch_bounds__(256) void k_final(const float* __restrict__ SW1,
                                               const float* __restrict__ Sb1,
                                               const float* __restrict__ SW2,
                                               const float* __restrict__ Sb2,
                                               float* __restrict__ out) {
    int i = blockIdx.x * blockDim.x + threadIdx.x;
    const float qT = __expf(-26.262166726f);    // 0.95^512
    const float aT = qT * 1.0010537407f;        // qT/(1-beta/eta)
    if (i < 512) {
        float s = 0.f;
        #pragma unroll
        for (int b = 0; b < Bz; b++) s += g_lossp[b*Tz + i];
        out[O_LOSS + i] = s * (1.f/512.f);
        return;
    }
    int j = i - 512;
    int ofD, nvec_b, segM, segS;
    const float* S0p;
    if (j < 16384) {
        ofD = OF2_W1D; nvec_b = 2048; segM = O_MW1; segS = O_SW1; S0p = SW1;
    } else if ((j -= 16384) < 256) {
        ofD = OF2_B1D; nvec_b = 32;   segM = O_MB1; segS = O_SB1; S0p = Sb1;
    } else if ((j -= 256) < 16384) {
        ofD = OF2_W2D; nvec_b = 2048; segM = O_MW2; segS = O_SW2; S0p = SW2;
    } else if ((j -= 16384) < 128) {
        ofD = OF2_B2D; nvec_b = 16;   segM = O_MB2; segS = O_SB2; S0p = Sb2;
    } else return;

    int b = j / nvec_b;
    int r = (j - b*nvec_b) * 4;
    const float* p = g_part + (size_t)(b*NC) * PARTSZ2 + ofD + r;
    float4 rD = make_float4(0.f, 0.f, 0.f, 0.f);
    #pragma unroll
    for (int c = 0; c < NC; c++) {
        float4 v = *(const float4*)(p + (size_t)c * PARTSZ2);
        rD.x += v.x; rD.y += v.y; rD.z += v.z; rD.w += v.w;
    }
    float4 cr = *(const float4*)(g_corr + (size_t)b * PARTSZ2 + ofD + r);
    int gidx = b * (nvec_b*4) + r;
    float4 s0 = *(const float4*)(S0p + gidx);
    float4 M, S;
    M.x = aT*s0.x + rD.x*INV949 + cr.x;  S.x = qT*s0.x + rD.x;
    M.y = aT*s0.y + rD.y*INV949 + cr.y;  S.y = qT*s0.y + rD.y;
    M.z = aT*s0.z + rD.z*INV949 + cr.z;  S.z = qT*s0.z + rD.z;
    M.w = aT*s0.w + rD.w*INV949 + cr.w;  S.w = qT*s0.w + rD.w;
    *(float4*)(out + segM + gidx) = M;
    *(float4*)(out + segS + gidx) = S;
}

extern "C" void kernel_launch(void* const* d_in, const int* in_sizes, int n_in,
                              void* d_out, int out_size) {
    const float* x   = (const float*)d_in[0];
    const float* WK  = (const float*)d_in[1];
    const float* WV  = (const float*)d_in[2];
    const float* W1  = (const float*)d_in[3];
    const float* b1  = (const float*)d_in[4];
    const float* W2  = (const float*)d_in[5];
    const float* b2  = (const float*)d_in[6];
    const float* SW1 = (const float*)d_in[7];
    const float* Sb1 = (const float*)d_in[8];
    const float* SW2 = (const float*)d_in[9];
    const float* Sb2 = (const float*)d_in[10];
    float* out = (float*)d_out;

    static const size_t smem_main = SM_FLOATS * sizeof(float);
    cudaFuncSetAttribute(k_main, cudaFuncAttributeMaxDynamicSharedMemorySize,
                         (int)smem_main);

    k_main<<<NCTA, 512, smem_main>>>(x, WK, WV, W1, b1, W2, b2);
    k_final<<<(33664 + 255) / 256, 256>>>(SW1, Sb1, SW2, Sb2, out);
}

// round 7
// speedup vs baseline: 14.1077x; 1.0077x over previous
#include <cuda_runtime.h>
#include <math.h>

// Problem constants
#define Bz 8
#define Tz 512
#define Ez 64
#define Hz 128
#define TC 32     // tokens per CTA
#define NC 16     // chunks per batch
#define NCTA (Bz*NC)

// Weight pitches (float4-aligned; pitch mod 32 == 4 -> conflict-free LDS.128)
#define P1 68
#define P2 132

// Per-CTA partial layout (floats): D-weighted grads only
#define OF2_W1D 0
#define OF2_B1D 8192
#define OF2_W2D 8320
#define OF2_B2D 16512
#define PARTSZ2 16576

// Output offsets
#define O_LOSS 0
#define O_MW1  512
#define O_MB1  66048
#define O_MW2  67072
#define O_MB2  132608
#define O_SW1  133120
#define O_SB1  198656
#define O_SW2  199680
#define O_SB2  265216

#define LNETA  (-0.0512932943875506f)
#define LNBETA (-6.9077552789821370f)
#define INV949 (1.0537407798735f)
#define CORRK  (0.0526870389936f)

// Scratch (device globals)
__device__ __align__(16) float g_np[2*NCTA*Ez];
__device__ __align__(16) float g_lossp[Bz*Tz];
__device__ __align__(16) float g_part[NCTA*PARTSZ2];
__device__ __align__(16) float g_corr[Bz*PARTSZ2];
__device__ unsigned g_count;           // self-resetting arrive counter
__device__ volatile unsigned g_phase;  // monotonic phase (replay-safe)

// Grid-wide sense barrier: call with all threads; tid0 spins, rest wait at bar.
__device__ __forceinline__ void grid_barrier(int tid) {
    __threadfence();
    __syncthreads();
    if (tid == 0) {
        unsigned my = g_phase;
        unsigned old = atomicAdd(&g_count, 1);
        if (old == NCTA - 1) {
            g_count = 0;
            __threadfence();
            atomicAdd((unsigned*)&g_phase, 1);
        } else {
            while (g_phase == my) { }
        }
        __threadfence();
    }
    __syncthreads();
}

// ---------------------------------------------------------------------------
// Single fused kernel. 128 CTAs x 512 threads, 143KB smem -> 1 CTA/SM,
// all co-resident. Two grid barriers: norms, then output reduction.
// ---------------------------------------------------------------------------
#define SM_FLOATS 35840
__global__ __launch_bounds__(512, 1) void k_main(const float* __restrict__ x,
                                                 const float* __restrict__ WK,
                                                 const float* __restrict__ WV,
                                                 const float* __restrict__ W1,
                                                 const float* __restrict__ b1,
                                                 const float* __restrict__ W2,
                                                 const float* __restrict__ b2,
                                                 const float* __restrict__ SW1,
                                                 const float* __restrict__ Sb1,
                                                 const float* __restrict__ SW2,
                                                 const float* __restrict__ Sb2,
                                                 float* __restrict__ out) {
    extern __shared__ float sm[];
    // Region A (8704): phase0 = WK|WV ; later = W1
    float* sWK  = sm;                 // 64 x P1
    float* sWV  = sm + 4352;          // 64 x P1
    float* sW1  = sm;                 // 128 x P1 overlay (WK/WV dead)
    // Region B (8448): phase0 = x ; later = W2
    float* sx   = sm + 8704;          // 32x64 (phase0 only)
    float* sW2  = sm + 8704;          // 64 x P2 overlay
    float* sk   = sm + 17152;         // 32x64
    float* sv   = sk  + 2048;         // 32x64
    float* sh   = sv  + 2048;         // 32x128
    float* ss   = sh  + 4096;         // 32x128
    float* sdy  = ss  + 4096;         // 32x64  (dedicated — no overlay)
    float* sdz  = sdy + 2048;         // 32x128 (dedicated)
    float* scD  = sdz + 4096;         // 32
    float* scC  = scD + 32;           // 32
    float* sinvk= scC + 32;           // 64
    float* sinvv= sinvk + 64;         // 64
    float* sloss= sinvv + 64;         // 32   -> total 35808 <= 35840

    const int bid = blockIdx.x;
    const int b   = bid >> 4;
    const int t0  = (bid & 15) * TC;
    const int tid = threadIdx.x;
    const int lane = tid & 31, wp = tid >> 5;   // 16 warps, 2 tokens each

    // ---- phase 0 loads ----
    #pragma unroll
    for (int i = tid*4; i < 4096; i += 2048) {
        int e = i >> 6, j = i & 63;
        *(float4*)&sWK[e*P1 + j] = *(const float4*)&WK[i];
        *(float4*)&sWV[e*P1 + j] = *(const float4*)&WV[i];
    }
    *(float4*)&sx[tid*4] = *(const float4*)&x[(b*Tz + t0)*64 + tid*4];
    if (tid < 64)       sinvk[tid] = 0.f;
    else if (tid < 128) sinvv[tid - 64] = 0.f;
    if (tid >= 128 && tid < 160) {
        int tl = tid - 128;
        float n1 = (float)(Tz - (t0 + tl));
        scD[tl] = -0.05f * __expf(n1 * LNETA);
        scC[tl] = CORRK  * __expf(n1 * LNBETA);
    }
    __syncthreads();

    // ---- phase 0: silu projections into smem ----
    {
        float acc[4][2];
        #pragma unroll
        for (int r = 0; r < 4; r++) { acc[r][0] = 0.f; acc[r][1] = 0.f; }
        for (int j = 0; j < 64; j += 4) {
            float xv[2][4];
            #pragma unroll
            for (int tt = 0; tt < 2; tt++) {
                float4 q = *(const float4*)&sx[(wp*2 + tt)*64 + j];
                xv[tt][0] = q.x; xv[tt][1] = q.y; xv[tt][2] = q.z; xv[tt][3] = q.w;
            }
            float4 w4[4];
            w4[0] = *(const float4*)&sWK[(lane     )*P1 + j];
            w4[1] = *(const float4*)&sWK[(lane + 32)*P1 + j];
            w4[2] = *(const float4*)&sWV[(lane     )*P1 + j];
            w4[3] = *(const float4*)&sWV[(lane + 32)*P1 + j];
            #pragma unroll
            for (int r = 0; r < 4; r++) {
                const float* w = (const float*)&w4[r];
                #pragma unroll
                for (int jj = 0; jj < 4; jj++) {
                    acc[r][0] += w[jj] * xv[0][jj];
                    acc[r][1] += w[jj] * xv[1][jj];
                }
            }
        }
        #pragma unroll
        for (int r = 0; r < 4; r++) {
            int e = lane + 32*(r & 1);
            float sq = 0.f;
            #pragma unroll
            for (int tt = 0; tt < 2; tt++) {
                float z = acc[r][tt];
                float s = z / (1.f + __expf(-z));
                int t = wp*2 + tt;
                if (r < 2) sk[t*64 + e] = s;
                else       sv[t*64 + e] = s;
                sq += s * s;
            }
            if (r < 2) atomicAdd(&sinvk[e], sq);
            else       atomicAdd(&sinvv[e], sq);
        }
    }
    __syncthreads();

    // publish norm partials
    if (tid < 64)       g_np[bid*64 + tid] = sinvk[tid];
    else if (tid < 128) g_np[(NCTA + bid)*64 + tid - 64] = sinvv[tid - 64];

    // ---- grid barrier #1 (W1/W2 loads overlap the spin) ----
    __threadfence();
    __syncthreads();
    if (tid == 0) {
        unsigned my = g_phase;
        unsigned old = atomicAdd(&g_count, 1);
        if (old == NCTA - 1) {
            g_count = 0;
            __threadfence();
            atomicAdd((unsigned*)&g_phase, 1);
        } else {
            while (g_phase == my) { }
        }
        __threadfence();
    }
    #pragma unroll
    for (int i = tid*4; i < 8192; i += 2048)
        *(float4*)&sW1[(i >> 6)*P1 + (i & 63)] = *(const float4*)&W1[b*8192 + i];
    #pragma unroll
    for (int i = tid*4; i < 8192; i += 2048)
        *(float4*)&sW2[(i >> 7)*P2 + (i & 127)] = *(const float4*)&W2[b*8192 + i];
    __syncthreads();

    // ---- reduce norms ----
    if (tid < 64) {
        float s = 0.f, s2 = 0.f;
        #pragma unroll
        for (int c = 0; c < NC; c++) {
            s  += g_np[(b*NC + c)*64 + tid];
            s2 += g_np[(NCTA + b*NC + c)*64 + tid];
        }
        sinvk[tid] = (s  > 0.f) ? rsqrtf(s)  : 0.f;
        sinvv[tid] = (s2 > 0.f) ? rsqrtf(s2) : 0.f;
    }
    __syncthreads();

    // ---- normalize k, v ----
    {
        int t = tid >> 4, e4 = (tid & 15) * 4;
        float4 q = *(const float4*)&sk[t*64 + e4];
        q.x *= sinvk[e4]; q.y *= sinvk[e4+1]; q.z *= sinvk[e4+2]; q.w *= sinvk[e4+3];
        *(float4*)&sk[t*64 + e4] = q;
        float4 p = *(const float4*)&sv[t*64 + e4];
        p.x *= sinvv[e4]; p.y *= sinvv[e4+1]; p.z *= sinvv[e4+2]; p.w *= sinvv[e4+3];
        *(float4*)&sv[t*64 + e4] = p;
    }
    __syncthreads();

    // ---- z = W1 k + b1 ; h = silu(z) ----  (warp-private rows from here)
    {
        float acc[4][2];
        #pragma unroll
        for (int r = 0; r < 4; r++) {
            float bv = b1[b*128 + lane + 32*r];
            acc[r][0] = bv; acc[r][1] = bv;
        }
        for (int j = 0; j < 64; j += 4) {
            float kv[2][4];
            #pragma unroll
            for (int tt = 0; tt < 2; tt++) {
                float4 q = *(const float4*)&sk[(wp*2 + tt)*64 + j];
                kv[tt][0] = q.x; kv[tt][1] = q.y; kv[tt][2] = q.z; kv[tt][3] = q.w;
            }
            float4 w4[4];
            #pragma unroll
            for (int r = 0; r < 4; r++)
                w4[r] = *(const float4*)&sW1[(lane + 32*r)*P1 + j];
            #pragma unroll
            for (int r = 0; r < 4; r++) {
                const float* w = (const float*)&w4[r];
                #pragma unroll
                for (int jj = 0; jj < 4; jj++) {
                    acc[r][0] += w[jj] * kv[0][jj];
                    acc[r][1] += w[jj] * kv[1][jj];
                }
            }
        }
        #pragma unroll
        for (int r = 0; r < 4; r++)
            #pragma unroll
            for (int tt = 0; tt < 2; tt++) {
                int idx = (wp*2 + tt)*128 + lane + 32*r;
                float z  = acc[r][tt];
                float sg = 1.f / (1.f + __expf(-z));
                ss[idx] = sg;
                sh[idx] = z * sg;
            }
    }
    __syncwarp();   // sh/ss rows are warp-private: warp-level sync suffices

    // ---- y = W2 h + b2 ; dy ; loss ----
    {
        float acc[2][2];
        #pragma unroll
        for (int r = 0; r < 2; r++) {
            float bv = b2[b*64 + lane + 32*r];
            acc[r][0] = bv; acc[r][1] = bv;
        }
        for (int j = 0; j < 128; j += 4) {
            float hv[2][4];
            #pragma unroll
            for (int tt = 0; tt < 2; tt++) {
                float4 q = *(const float4*)&sh[(wp*2 + tt)*128 + j];
                hv[tt][0] = q.x; hv[tt][1] = q.y; hv[tt][2] = q.z; hv[tt][3] = q.w;
            }
            float4 w40 = *(const float4*)&sW2[(lane     )*P2 + j];
            float4 w41 = *(const float4*)&sW2[(lane + 32)*P2 + j];
            const float* w0 = (const float*)&w40;
            const float* w1 = (const float*)&w41;
            #pragma unroll
            for (int jj = 0; jj < 4; jj++) {
                acc[0][0] += w0[jj] * hv[0][jj];
                acc[0][1] += w0[jj] * hv[1][jj];
                acc[1][0] += w1[jj] * hv[0][jj];
                acc[1][1] += w1[jj] * hv[1][jj];
            }
        }
        #pragma unroll
        for (int tt = 0; tt < 2; tt++) {
            int t = wp*2 + tt;
            float l = 0.f;
            #pragma unroll
            for (int r = 0; r < 2; r++) {
                int e = lane + 32*r;
                float d = acc[r][tt] - sv[t*64 + e];
                sdy[t*64 + e] = d * (1.f/256.f);
                l += d * d;
            }
            #pragma unroll
            for (int o = 16; o; o >>= 1) l += __shfl_xor_sync(0xffffffffu, l, o);
            if (lane == 0) sloss[t] = l;
        }
    }
    __syncwarp();   // sdy rows warp-private

    // ---- dh = W2^T dy ; dz ----
    {
        float acc[4][2];
        #pragma unroll
        for (int r = 0; r < 4; r++) { acc[r][0] = 0.f; acc[r][1] = 0.f; }
        for (int e = 0; e < 64; e += 4) {
            float dv[2][4];
            #pragma unroll
            for (int tt = 0; tt < 2; tt++) {
                float4 q = *(const float4*)&sdy[(wp*2 + tt)*64 + e];
                dv[tt][0] = q.x; dv[tt][1] = q.y; dv[tt][2] = q.z; dv[tt][3] = q.w;
            }
            #pragma unroll
            for (int ee = 0; ee < 4; ee++) {
                float wv[4];
                #pragma unroll
                for (int r = 0; r < 4; r++) wv[r] = sW2[(e + ee)*P2 + lane + 32*r];
                #pragma unroll
                for (int r = 0; r < 4; r++) {
                    acc[r][0] += wv[r] * dv[0][ee];
                    acc[r][1] += wv[r] * dv[1][ee];
                }
            }
        }
        #pragma unroll
        for (int r = 0; r < 4; r++)
            #pragma unroll
            for (int tt = 0; tt < 2; tt++) {
                int idx = (wp*2 + tt)*128 + lane + 32*r;
                float sg = ss[idx], hv = sh[idx];
                sdz[idx] = acc[r][tt] * (sg + hv * (1.f - sg));
            }
    }
    __syncthreads();   // outer phase reads all tokens

    // ---- D-weighted outer products ----
    const int e0 = (tid & 15) * 4;
    const int h0 = (tid >> 4) * 4;
    float a1[4][4], a2[4][4];
    #pragma unroll
    for (int i = 0; i < 4; i++)
        #pragma unroll
        for (int j = 0; j < 4; j++) { a1[i][j] = 0.f; a2[j][i] = 0.f; }

    for (int t = 0; t < TC; t++) {
        float cd = scD[t];
        float4 kq = *(const float4*)&sk[t*64 + e0];
        float ks[4] = {cd*kq.x, cd*kq.y, cd*kq.z, cd*kq.w};
        float4 zq = *(const float4*)&sdz[t*128 + h0];
        float dzv[4] = {zq.x, zq.y, zq.z, zq.w};
        #pragma unroll
        for (int i = 0; i < 4; i++)
            #pragma unroll
            for (int j = 0; j < 4; j++) a1[i][j] += dzv[i] * ks[j];
        float4 dq = *(const float4*)&sdy[t*64 + e0];
        float dys[4] = {cd*dq.x, cd*dq.y, cd*dq.z, cd*dq.w};
        float4 hq = *(const float4*)&sh[t*128 + h0];
        float hv[4] = {hq.x, hq.y, hq.z, hq.w};
        #pragma unroll
        for (int j = 0; j < 4; j++)
            #pragma unroll
            for (int i = 0; i < 4; i++) a2[j][i] += dys[j] * hv[i];
    }

    float* p = g_part + (size_t)bid * PARTSZ2;
    #pragma unroll
    for (int i = 0; i < 4; i++)
        *(float4*)&p[OF2_W1D + (h0 + i)*64 + e0] =
            make_float4(a1[i][0], a1[i][1], a1[i][2], a1[i][3]);
    #pragma unroll
    for (int j = 0; j < 4; j++)
        *(float4*)&p[OF2_W2D + (e0 + j)*128 + h0] =
            make_float4(a2[j][0], a2[j][1], a2[j][2], a2[j][3]);
    if (tid < 128) {
        float aD = 0.f;
        for (int t = 0; t < TC; t++) aD += scD[t] * sdz[t*128 + tid];
        p[OF2_B1D + tid] = aD;
    } else if (tid < 192) {
        int e = tid - 128;
        float aD = 0.f;
        for (int t = 0; t < TC; t++) aD += scD[t] * sdy[t*64 + e];
        p[OF2_B2D + e] = aD;
    }
    if (tid < TC) g_lossp[b*Tz + t0 + tid] = sloss[tid];

    // ---- correction (last chunk per batch) ----
    if ((bid & 15) == 15) {
        #pragma unroll
        for (int i = 0; i < 4; i++)
            #pragma unroll
            for (int j = 0; j < 4; j++) { a1[i][j] = 0.f; a2[j][i] = 0.f; }
        for (int t = 16; t < TC; t++) {
            float cc = scC[t];
            float4 kq = *(const float4*)&sk[t*64 + e0];
            float ks[4] = {cc*kq.x, cc*kq.y, cc*kq.z, cc*kq.w};
            float4 zq = *(const float4*)&sdz[t*128 + h0];
            float dzv[4] = {zq.x, zq.y, zq.z, zq.w};
            #pragma unroll
            for (int i = 0; i < 4; i++)
                #pragma unroll
                for (int j = 0; j < 4; j++) a1[i][j] += dzv[i] * ks[j];
            float4 dq = *(const float4*)&sdy[t*64 + e0];
            float dys[4] = {cc*dq.x, cc*dq.y, cc*dq.z, cc*dq.w};
            float4 hq = *(const float4*)&sh[t*128 + h0];
            float hv[4] = {hq.x, hq.y, hq.z, hq.w};
            #pragma unroll
            for (int j = 0; j < 4; j++)
                #pragma unroll
                for (int i = 0; i < 4; i++) a2[j][i] += dys[j] * hv[i];
        }
        float* q = g_corr + (size_t)b * PARTSZ2;
        #pragma unroll
        for (int i = 0; i < 4; i++)
            *(float4*)&q[OF2_W1D + (h0 + i)*64 + e0] =
                make_float4(a1[i][0], a1[i][1], a1[i][2], a1[i][3]);
        #pragma unroll
        for (int j = 0; j < 4; j++)
            *(float4*)&q[OF2_W2D + (e0 + j)*128 + h0] =
                make_float4(a2[j][0], a2[j][1], a2[j][2], a2[j][3]);
        if (tid < 128) {
            float aC = 0.f;
            for (int t = 16; t < TC; t++) aC += scC[t] * sdz[t*128 + tid];
            q[OF2_B1D + tid] = aC;
        } else if (tid < 192) {
            int e = tid - 128;
            float aC = 0.f;
            for (int t = 16; t < TC; t++) aC += scC[t] * sdy[t*64 + e];
            q[OF2_B2D + e] = aC;
        }
    }

    // ---- grid barrier #2, then fused output reduction (partials L2-hot) ----
    grid_barrier(tid);

    const float qT = __expf(-26.262166726f);    // 0.95^512
    const float aT = qT * 1.0010537407f;        // qT/(1-beta/eta)
    int gt = bid * 512 + tid;                   // 65536 threads >= 33664 items
    if (gt < 512) {
        float s = 0.f;
        #pragma unroll
        for (int bb = 0; bb < Bz; bb++) s += g_lossp[bb*Tz + gt];
        out[O_LOSS + gt] = s * (1.f/512.f);
        return;
    }
    int j = gt - 512;
    int ofD, nvec_b, segM, segS;
    const float* S0p;
    if (j < 16384) {
        ofD = OF2_W1D; nvec_b = 2048; segM = O_MW1; segS = O_SW1; S0p = SW1;
    } else if ((j -= 16384) < 256) {
        ofD = OF2_B1D; nvec_b = 32;   segM = O_MB1; segS = O_SB1; S0p = Sb1;
    } else if ((j -= 256) < 16384) {
        ofD = OF2_W2D; nvec_b = 2048; segM = O_MW2; segS = O_SW2; S0p = SW2;
    } else if ((j -= 16384) < 128) {
        ofD = OF2_B2D; nvec_b = 16;   segM = O_MB2; segS = O_SB2; S0p = Sb2;
    } else return;

    int bb = j / nvec_b;
    int r = (j - bb*nvec_b) * 4;
    const float* pp = g_part + (size_t)(bb*NC) * PARTSZ2 + ofD + r;
    float4 rD = make_float4(0.f, 0.f, 0.f, 0.f);
    #pragma unroll
    for (int c = 0; c < NC; c++) {
        float4 v = *(const float4*)(pp + (size_t)c * PARTSZ2);
        rD.x += v.x; rD.y += v.y; rD.z += v.z; rD.w += v.w;
    }
    float4 cr = *(const float4*)(g_corr + (size_t)bb * PARTSZ2 + ofD + r);
    int gidx = bb * (nvec_b*4) + r;
    float4 s0 = *(const float4*)(S0p + gidx);
    float4 M, S;
    M.x = aT*s0.x + rD.x*INV949 + cr.x;  S.x = qT*s0.x + rD.x;
    M.y = aT*s0.y + rD.y*INV949 + cr.y;  S.y = qT*s0.y + rD.y;
    M.z = aT*s0.z + rD.z*INV949 + cr.z;  S.z = qT*s0.z + rD.z;
    M.w = aT*s0.w + rD.w*INV949 + cr.w;  S.w = qT*s0.w + rD.w;
    *(float4*)(out + segM + gidx) = M;
    *(float4*)(out + segS + gidx) = S;
}

extern "C" void kernel_launch(void* const* d_in, const int* in_sizes, int n_in,
                              void* d_out, int out_size) {
    const float* x   = (const float*)d_in[0];
    const float* WK  = (const float*)d_in[1];
    const float* WV  = (const float*)d_in[2];
    const float* W1  = (const float*)d_in[3];
    const float* b1  = (const float*)d_in[4];
    const float* W2  = (const float*)d_in[5];
    const float* b2  = (const float*)d_in[6];
    const float* SW1 = (const float*)d_in[7];
    const float* Sb1 = (const float*)d_in[8];
    const float* SW2 = (const float*)d_in[9];
    const float* Sb2 = (const float*)d_in[10];
    float* out = (float*)d_out;

    static const size_t smem_main = SM_FLOATS * sizeof(float);
    cudaFuncSetAttribute(k_main, cudaFuncAttributeMaxDynamicSharedMemorySize,
                         (int)smem_main);

    k_main<<<NCTA, 512, smem_main>>>(x, WK, WV, W1, b1, W2, b2,
                                     SW1, Sb1, SW2, Sb2, out);
}